// round 12
// baseline (speedup 1.0000x reference)
#include <cuda_runtime.h>
#include <cuda_bf16.h>
#include <stdint.h>

// Problem dims (fixed)
#define B_NUM 4
#define S_LEN 2048
#define D_DIM 1024
#define H_NUM 16
#define DH 64
#define MROWS (B_NUM * S_LEN)   // 8192

// bf16 split operands
__device__ __nv_bfloat16 g_xh[MROWS * D_DIM];
__device__ __nv_bfloat16 g_xl[MROWS * D_DIM];
__device__ __nv_bfloat16 g_qh[MROWS * D_DIM];
__device__ __nv_bfloat16 g_ql[MROWS * D_DIM];
__device__ __nv_bfloat16 g_kh[MROWS * D_DIM];
__device__ __nv_bfloat16 g_kl[MROWS * D_DIM];
__device__ __nv_bfloat16 g_vh[MROWS * D_DIM];
__device__ __nv_bfloat16 g_vl[MROWS * D_DIM];
__device__ __nv_bfloat16 g_zh[MROWS * D_DIM];
__device__ __nv_bfloat16 g_zl[MROWS * D_DIM];
// transposed weights [n][k], hi/lo, for Wq,Wk,Wv,Wout (contiguous rows 0..4095)
__device__ __nv_bfloat16 g_wth[4][D_DIM * D_DIM];
__device__ __nv_bfloat16 g_wtl[4][D_DIM * D_DIM];

// ---------------------------------------------------------------------------
// Helpers
// ---------------------------------------------------------------------------
__device__ __forceinline__ uint32_t smem_u32(const void* p) {
    uint32_t a;
    asm("{ .reg .u64 t; cvta.to.shared.u64 t, %1; cvt.u32.u64 %0, t; }" : "=r"(a) : "l"(p));
    return a;
}
#define SW128(off) ((off) ^ (((off) >> 3) & 0x70))
__device__ __forceinline__ void cpa16(uint32_t s, const void* g) {
    asm volatile("cp.async.cg.shared.global [%0], [%1], 16;" :: "r"(s), "l"(__cvta_generic_to_global(g)));
}
#define CP_COMMIT() asm volatile("cp.async.commit_group;" ::: "memory")
template <int N> __device__ __forceinline__ void cp_wait() {
    asm volatile("cp.async.wait_group %0;" :: "n"(N) : "memory");
}
__device__ __forceinline__ void ldsm4(uint32_t* r, uint32_t addr) {
    asm volatile("ldmatrix.sync.aligned.m8n8.x4.shared.b16 {%0,%1,%2,%3}, [%4];"
                 : "=r"(r[0]), "=r"(r[1]), "=r"(r[2]), "=r"(r[3]) : "r"(addr));
}
__device__ __forceinline__ void ldsm4t(uint32_t* r, uint32_t addr) {
    asm volatile("ldmatrix.sync.aligned.m8n8.x4.trans.shared.b16 {%0,%1,%2,%3}, [%4];"
                 : "=r"(r[0]), "=r"(r[1]), "=r"(r[2]), "=r"(r[3]) : "r"(addr));
}
__device__ __forceinline__ void mma_bf16(float* c, const uint32_t* a, uint32_t b0, uint32_t b1) {
    asm volatile("mma.sync.aligned.m16n8k16.row.col.f32.bf16.bf16.f32 "
                 "{%0,%1,%2,%3}, {%4,%5,%6,%7}, {%8,%9}, {%0,%1,%2,%3};"
                 : "+f"(c[0]), "+f"(c[1]), "+f"(c[2]), "+f"(c[3])
                 : "r"(a[0]), "r"(a[1]), "r"(a[2]), "r"(a[3]), "r"(b0), "r"(b1));
}
__device__ __forceinline__ void split_pack(float x0, float x1, uint32_t& hp, uint32_t& lp) {
    const uint32_t b0 = __float_as_uint(x0), b1 = __float_as_uint(x1);
    hp = __byte_perm(b0, b1, 0x7632);
    const float l0 = x0 - __uint_as_float(b0 & 0xFFFF0000u);
    const float l1 = x1 - __uint_as_float(b1 & 0xFFFF0000u);
    const __nv_bfloat162 lv = __float22bfloat162_rn(make_float2(l0, l1));
    lp = *(const uint32_t*)&lv;
}
__device__ __forceinline__ float ex2_mufu(float y) {
    float r; asm("ex2.approx.f32 %0, %1;" : "=f"(r) : "f"(y)); return r;
}

// ---------------------------------------------------------------------------
// Conversion kernels
// ---------------------------------------------------------------------------
__global__ void k_split(const float* __restrict__ x, __nv_bfloat16* __restrict__ h,
                        __nv_bfloat16* __restrict__ l, int n) {
    int i = blockIdx.x * blockDim.x + threadIdx.x;
    if (i < n) {
        const float v = x[i];
        const __nv_bfloat16 hh = __float2bfloat16(v);
        h[i] = hh;
        l[i] = __float2bfloat16(v - __bfloat162float(hh));
    }
}
__global__ void k_tsplit4(const float* __restrict__ W0, const float* __restrict__ W1,
                          const float* __restrict__ W2, const float* __restrict__ W3,
                          __nv_bfloat16* __restrict__ Th, __nv_bfloat16* __restrict__ Tl) {
    __shared__ float t[32][33];
    const int w = blockIdx.z;
    const float* W = (w == 0) ? W0 : (w == 1) ? W1 : (w == 2) ? W2 : W3;
    const size_t obase = (size_t)w * D_DIM * D_DIM;
    const int n0 = blockIdx.x * 32, k0 = blockIdx.y * 32;
    const int x = threadIdx.x, y = threadIdx.y;  // blockDim (32,8)
#pragma unroll
    for (int r = 0; r < 32; r += 8)
        t[y + r][x] = W[(size_t)(k0 + y + r) * D_DIM + n0 + x];
    __syncthreads();
#pragma unroll
    for (int r = 0; r < 32; r += 8) {
        const float v = t[x][y + r];
        const __nv_bfloat16 hh = __float2bfloat16(v);
        const size_t off = obase + (size_t)(n0 + y + r) * D_DIM + k0 + x;
        Th[off] = hh;
        Tl[off] = __float2bfloat16(v - __bfloat162float(hh));
    }
}

// ---------------------------------------------------------------------------
// mma.sync split-bf16 GEMM, 3-stage pipeline.
// R12: 4 warps (128 thr), 64x64 warp tiles (2x2 warp grid) — halves ldsm
// traffic per stage (128KB vs 192KB) so the smem port is no longer binding.
// ---------------------------------------------------------------------------
#define TILE_M 128
#define TILE_N 128
#define BK 64
#define NITER (D_DIM / BK)          // 16
#define OFF_AH 0
#define OFF_AL 16384
#define OFF_BH 32768
#define OFF_BL 49152
#define STAGE_BYTES 65536
#define GEMM_SMEM (3 * STAGE_BYTES)   // 192KB

__device__ __forceinline__ void gemm_loads(
    uint32_t sbase, int tid, int kt, int m0, int n0,
    const __nv_bfloat16* Ah, const __nv_bfloat16* Al,
    const __nv_bfloat16* Bh, const __nv_bfloat16* Bl)
{
    const int k0 = kt * BK;
#pragma unroll
    for (int c = tid; c < 1024; c += 128) {
        const int row = c >> 3, kc = c & 7;
        const uint32_t sw = SW128((uint32_t)(row * 128 + kc * 16));
        const size_t ga = (size_t)(m0 + row) * D_DIM + k0 + kc * 8;
        const size_t gb = (size_t)(n0 + row) * D_DIM + k0 + kc * 8;
        cpa16(sbase + OFF_AH + sw, Ah + ga);
        cpa16(sbase + OFF_AL + sw, Al + ga);
        cpa16(sbase + OFF_BH + sw, Bh + gb);
        cpa16(sbase + OFF_BL + sw, Bl + gb);
    }
    CP_COMMIT();
}

__global__ __launch_bounds__(128, 1)
void gemm_mma3(const __nv_bfloat16* __restrict__ Ah, const __nv_bfloat16* __restrict__ Al,
               const __nv_bfloat16* __restrict__ Bh, const __nv_bfloat16* __restrict__ Bl,
               const float* __restrict__ resid, float* __restrict__ Cf,
               __nv_bfloat16* __restrict__ O0h, __nv_bfloat16* __restrict__ O0l,
               __nv_bfloat16* __restrict__ O1h, __nv_bfloat16* __restrict__ O1l,
               __nv_bfloat16* __restrict__ O2h, __nv_bfloat16* __restrict__ O2l)
{
    extern __shared__ __align__(128) char smem[];
    const uint32_t sb = smem_u32(smem);
    const int tid = threadIdx.x, wid = tid >> 5, lane = tid & 31;
    const int warp_m = wid & 1;        // 2 warps over M: 64 rows each
    const int warp_n = wid >> 1;       // 2 warps over N: 64 cols each
    const int n0 = blockIdx.x * TILE_N;
    const int m0 = blockIdx.y * TILE_M;

    float acc[4][8][4];
#pragma unroll
    for (int mt = 0; mt < 4; mt++)
#pragma unroll
        for (int nt = 0; nt < 8; nt++)
#pragma unroll
            for (int i = 0; i < 4; i++) acc[mt][nt][i] = 0.f;

    gemm_loads(sb, tid, 0, m0, n0, Ah, Al, Bh, Bl);
    gemm_loads(sb + STAGE_BYTES, tid, 1, m0, n0, Ah, Al, Bh, Bl);
    cp_wait<1>();
    __syncthreads();

    const int arow = warp_m * 64 + (lane & 15);          // + mt*16
    const uint32_t acolb = (uint32_t)((lane >> 4) << 4);
    const int brow = warp_n * 64 + ((lane >> 4) << 3) + (lane & 7);  // + p*16
    const uint32_t bcolb = (uint32_t)(((lane >> 3) & 1) << 4);

    for (int it = 0; it < NITER; it++) {
        if (it + 2 < NITER)
            gemm_loads(sb + ((it + 2) % 3) * STAGE_BYTES, tid, it + 2, m0, n0, Ah, Al, Bh, Bl);

        const uint32_t s0 = sb + (it % 3) * STAGE_BYTES;
#pragma unroll
        for (int ks = 0; ks < 4; ks++) {
            const uint32_t kb = (uint32_t)(ks * 32);
            uint32_t ah[4][4], al[4][4];
#pragma unroll
            for (int mt = 0; mt < 4; mt++) {
                const uint32_t off = SW128((uint32_t)((arow + mt * 16) * 128) + kb + acolb);
                ldsm4(ah[mt], s0 + OFF_AH + off);
                ldsm4(al[mt], s0 + OFF_AL + off);
            }
            uint32_t bh[4][4], bl[4][4];   // [p]: regs for nt=2p (b0,b1), nt=2p+1 (b0,b1)
#pragma unroll
            for (int p = 0; p < 4; p++) {
                const uint32_t off = SW128((uint32_t)((brow + p * 16) * 128) + kb + bcolb);
                ldsm4(bh[p], s0 + OFF_BH + off);
                ldsm4(bl[p], s0 + OFF_BL + off);
            }
#pragma unroll
            for (int mt = 0; mt < 4; mt++)
#pragma unroll
                for (int p = 0; p < 4; p++)
#pragma unroll
                    for (int hf = 0; hf < 2; hf++) {
                        float* c = acc[mt][p * 2 + hf];
                        mma_bf16(c, ah[mt], bh[p][hf * 2], bh[p][hf * 2 + 1]);
                        mma_bf16(c, ah[mt], bl[p][hf * 2], bl[p][hf * 2 + 1]);
                        mma_bf16(c, al[mt], bh[p][hf * 2], bh[p][hf * 2 + 1]);
                    }
        }

        if (it + 2 < NITER) cp_wait<1>(); else cp_wait<0>();
        __syncthreads();
    }

    const int sel = n0 >> 10;
    const int nl = n0 & (D_DIM - 1);
    __nv_bfloat16* Oh = (sel == 0) ? O0h : (sel == 1) ? O1h : O2h;
    __nv_bfloat16* Ol = (sel == 0) ? O0l : (sel == 1) ? O1l : O2l;
#pragma unroll
    for (int mt = 0; mt < 4; mt++) {
        const int row0 = m0 + warp_m * 64 + mt * 16 + (lane >> 2);
#pragma unroll
        for (int nt = 0; nt < 8; nt++) {
            const int coll = nl + warp_n * 64 + nt * 8 + (lane & 3) * 2;
            const float* c = acc[mt][nt];
            const size_t off = (size_t)row0 * D_DIM + coll;
            if (Cf) {
                float2 v0 = make_float2(c[0], c[1]);
                float2 v1 = make_float2(c[2], c[3]);
                if (resid) {
                    const float2 r0 = *(const float2*)&resid[off];
                    const float2 r1 = *(const float2*)&resid[off + 8 * D_DIM];
                    v0.x += r0.x; v0.y += r0.y; v1.x += r1.x; v1.y += r1.y;
                }
                *(float2*)&Cf[off] = v0;
                *(float2*)&Cf[off + 8 * D_DIM] = v1;
            } else {
                uint32_t hp, lp;
                split_pack(c[0], c[1], hp, lp);
                *(uint32_t*)&Oh[off] = hp; *(uint32_t*)&Ol[off] = lp;
                split_pack(c[2], c[3], hp, lp);
                *(uint32_t*)&Oh[off + 8 * D_DIM] = hp; *(uint32_t*)&Ol[off + 8 * D_DIM] = lp;
            }
        }
    }
}

// ---------------------------------------------------------------------------
// Tensor-core flash attention (R11 validated) — unchanged.
// 64 q-rows / 128 threads / 4 warps per CTA, 2 CTAs per SM.
// ---------------------------------------------------------------------------
#define ATT_SMEM (16384 + 3 * 32768)   // 114688
#define SLOG2E 0.1803368801111204f     // 0.125 * log2(e)
#define NKV (S_LEN / 64)               // 32

__device__ __forceinline__ void attn_kv_load(
    uint32_t sbase, int tid, size_t kvbase, int k0,
    const __nv_bfloat16* kh, const __nv_bfloat16* kl,
    const __nv_bfloat16* vh, const __nv_bfloat16* vl)
{
#pragma unroll
    for (int c = tid; c < 512; c += 128) {
        const int row = c >> 3, ch = c & 7;
        const uint32_t sw = SW128((uint32_t)(row * 128 + ch * 16));
        const size_t g = kvbase + (size_t)(k0 + row) * D_DIM + ch * 8;
        cpa16(sbase + sw, kh + g);
        cpa16(sbase + 8192 + sw, kl + g);
        cpa16(sbase + 16384 + sw, vh + g);
        cpa16(sbase + 24576 + sw, vl + g);
    }
    CP_COMMIT();
}

__global__ __launch_bounds__(128, 2)
void attn_mma(const __nv_bfloat16* __restrict__ qh, const __nv_bfloat16* __restrict__ ql,
              const __nv_bfloat16* __restrict__ kh, const __nv_bfloat16* __restrict__ kl,
              const __nv_bfloat16* __restrict__ vh, const __nv_bfloat16* __restrict__ vl,
              __nv_bfloat16* __restrict__ zh, __nv_bfloat16* __restrict__ zl)
{
    extern __shared__ __align__(128) char smem[];
    const uint32_t sb = smem_u32(smem);
    const int tid = threadIdx.x, wid = tid >> 5, lane = tid & 31;
    const int q0 = blockIdx.x * 64;
    const int h = blockIdx.y, b = blockIdx.z;
    const size_t qbase = ((size_t)(b * S_LEN + q0)) * D_DIM + h * DH;
    const size_t kvbase = ((size_t)b * S_LEN) * D_DIM + h * DH;

#pragma unroll
    for (int c = tid; c < 512; c += 128) {
        const int row = c >> 3, ch = c & 7;
        const uint32_t sw = SW128((uint32_t)(row * 128 + ch * 16));
        const size_t g = qbase + (size_t)row * D_DIM + ch * 8;
        cpa16(sb + sw, qh + g);
        cpa16(sb + 8192 + sw, ql + g);
    }
    CP_COMMIT();
    attn_kv_load(sb + 16384, tid, kvbase, 0, kh, kl, vh, vl);
    attn_kv_load(sb + 16384 + 32768, tid, kvbase, 64, kh, kl, vh, vl);
    cp_wait<1>();
    __syncthreads();

    const int arow = wid * 16 + (lane & 15);
    const uint32_t acolb = (uint32_t)((lane >> 4) << 4);
    const int bnrow = ((lane >> 4) << 3) + (lane & 7);
    const uint32_t bncol = (uint32_t)(((lane >> 3) & 1) << 4);
    const int vrow = ((lane >> 3) & 1) * 8 + (lane & 7);
    const uint32_t vcolb = (uint32_t)((lane >> 4) << 4);

    uint32_t qfh[4][4], qfl[4][4];
#pragma unroll
    for (int ks = 0; ks < 4; ks++) {
        const uint32_t off = SW128((uint32_t)(arow * 128) + (uint32_t)(ks * 32) + acolb);
        ldsm4(qfh[ks], sb + off);
        ldsm4(qfl[ks], sb + 8192 + off);
    }

    float O[8][4];
#pragma unroll
    for (int nt = 0; nt < 8; nt++)
#pragma unroll
        for (int i = 0; i < 4; i++) O[nt][i] = 0.f;
    float m0 = -1.0e30f, m1 = -1.0e30f, l0 = 0.f, l1 = 0.f;

    for (int t = 0; t < NKV; t++) {
        if (t + 2 < NKV)
            attn_kv_load(sb + 16384 + ((t + 2) % 3) * 32768, tid, kvbase, (t + 2) * 64, kh, kl, vh, vl);

        const uint32_t kbB = sb + 16384 + (t % 3) * 32768;

        float S[8][4];
#pragma unroll
        for (int nt = 0; nt < 8; nt++)
#pragma unroll
            for (int i = 0; i < 4; i++) S[nt][i] = 0.f;
#pragma unroll
        for (int ks = 0; ks < 4; ks++) {
            uint32_t bh_[4][4], bl_[4][4];
#pragma unroll
            for (int p = 0; p < 4; p++) {
                const uint32_t off = SW128((uint32_t)((p * 16 + bnrow) * 128) + (uint32_t)(ks * 32) + bncol);
                ldsm4(bh_[p], kbB + off);
                ldsm4(bl_[p], kbB + 8192 + off);
            }
#pragma unroll
            for (int p = 0; p < 4; p++)
#pragma unroll
                for (int hf = 0; hf < 2; hf++) {
                    float* c = S[p * 2 + hf];
                    mma_bf16(c, qfh[ks], bh_[p][hf * 2], bh_[p][hf * 2 + 1]);
                    mma_bf16(c, qfh[ks], bl_[p][hf * 2], bl_[p][hf * 2 + 1]);
                    mma_bf16(c, qfl[ks], bh_[p][hf * 2], bh_[p][hf * 2 + 1]);
                }
        }

        float mx0 = -1.0e30f, mx1 = -1.0e30f;
#pragma unroll
        for (int nt = 0; nt < 8; nt++) {
            mx0 = fmaxf(mx0, fmaxf(S[nt][0], S[nt][1]));
            mx1 = fmaxf(mx1, fmaxf(S[nt][2], S[nt][3]));
        }
        mx0 = fmaxf(mx0, __shfl_xor_sync(0xffffffffu, mx0, 1));
        mx0 = fmaxf(mx0, __shfl_xor_sync(0xffffffffu, mx0, 2));
        mx1 = fmaxf(mx1, __shfl_xor_sync(0xffffffffu, mx1, 1));
        mx1 = fmaxf(mx1, __shfl_xor_sync(0xffffffffu, mx1, 2));
        const float mn0 = fmaxf(m0, mx0), mn1 = fmaxf(m1, mx1);
        const float mb0 = mn0 * SLOG2E, mb1 = mn1 * SLOG2E;
        const float a0 = ex2_mufu(fmaf(m0, SLOG2E, -mb0));
        const float a1 = ex2_mufu(fmaf(m1, SLOG2E, -mb1));
        m0 = mn0; m1 = mn1;

        float s0 = 0.f, s1 = 0.f;
#pragma unroll
        for (int nt = 0; nt < 8; nt++) {
            S[nt][0] = ex2_mufu(fmaf(S[nt][0], SLOG2E, -mb0));
            S[nt][1] = ex2_mufu(fmaf(S[nt][1], SLOG2E, -mb0));
            S[nt][2] = ex2_mufu(fmaf(S[nt][2], SLOG2E, -mb1));
            S[nt][3] = ex2_mufu(fmaf(S[nt][3], SLOG2E, -mb1));
            s0 += S[nt][0] + S[nt][1];
            s1 += S[nt][2] + S[nt][3];
        }
        l0 = l0 * a0 + s0;
        l1 = l1 * a1 + s1;

        if (__ballot_sync(0xffffffffu, (a0 != 1.0f) || (a1 != 1.0f))) {
#pragma unroll
            for (int nt = 0; nt < 8; nt++) {
                O[nt][0] *= a0; O[nt][1] *= a0; O[nt][2] *= a1; O[nt][3] *= a1;
            }
        }

        uint32_t pfh[4][4], pfl[4][4];
#pragma unroll
        for (int ks = 0; ks < 4; ks++) {
            split_pack(S[2 * ks][0], S[2 * ks][1], pfh[ks][0], pfl[ks][0]);
            split_pack(S[2 * ks][2], S[2 * ks][3], pfh[ks][1], pfl[ks][1]);
            split_pack(S[2 * ks + 1][0], S[2 * ks + 1][1], pfh[ks][2], pfl[ks][2]);
            split_pack(S[2 * ks + 1][2], S[2 * ks + 1][3], pfh[ks][3], pfl[ks][3]);
        }

#pragma unroll
        for (int ks = 0; ks < 4; ks++) {
            uint32_t vh_[4][4], vl_[4][4];
#pragma unroll
            for (int p = 0; p < 4; p++) {
                const uint32_t off = SW128((uint32_t)((ks * 16 + vrow) * 128) + (uint32_t)(p * 32) + vcolb);
                ldsm4t(vh_[p], kbB + 16384 + off);
                ldsm4t(vl_[p], kbB + 24576 + off);
            }
#pragma unroll
            for (int p = 0; p < 4; p++)
#pragma unroll
                for (int hf = 0; hf < 2; hf++) {
                    float* o = O[p * 2 + hf];
                    mma_bf16(o, pfh[ks], vh_[p][hf * 2], vh_[p][hf * 2 + 1]);
                    mma_bf16(o, pfh[ks], vl_[p][hf * 2], vl_[p][hf * 2 + 1]);
                    mma_bf16(o, pfl[ks], vh_[p][hf * 2], vh_[p][hf * 2 + 1]);
                }
        }

        if (t + 2 < NKV) cp_wait<1>(); else cp_wait<0>();
        __syncthreads();
    }

    l0 += __shfl_xor_sync(0xffffffffu, l0, 1);
    l0 += __shfl_xor_sync(0xffffffffu, l0, 2);
    l1 += __shfl_xor_sync(0xffffffffu, l1, 1);
    l1 += __shfl_xor_sync(0xffffffffu, l1, 2);
    const float inv0 = 1.0f / l0, inv1 = 1.0f / l1;

    const int rowg = b * S_LEN + q0 + wid * 16 + (lane >> 2);
#pragma unroll
    for (int nt = 0; nt < 8; nt++) {
        const int col = h * DH + nt * 8 + (lane & 3) * 2;
        uint32_t hp, lp;
        split_pack(O[nt][0] * inv0, O[nt][1] * inv0, hp, lp);
        size_t off = (size_t)rowg * D_DIM + col;
        *(uint32_t*)&zh[off] = hp; *(uint32_t*)&zl[off] = lp;
        split_pack(O[nt][2] * inv1, O[nt][3] * inv1, hp, lp);
        off += (size_t)8 * D_DIM;
        *(uint32_t*)&zh[off] = hp; *(uint32_t*)&zl[off] = lp;
    }
}

// ---------------------------------------------------------------------------
// Inputs (metadata order): x, mask(bool, unused), Wq, Wk, Wv, Wout
// ---------------------------------------------------------------------------
extern "C" void kernel_launch(void* const* d_in, const int* in_sizes, int n_in,
                              void* d_out, int out_size)
{
    (void)in_sizes; (void)n_in; (void)out_size;
    const float* x    = (const float*)d_in[0];
    const float* Wq   = (const float*)d_in[2];
    const float* Wk   = (const float*)d_in[3];
    const float* Wv   = (const float*)d_in[4];
    const float* Wout = (const float*)d_in[5];
    float* out = (float*)d_out;

    __nv_bfloat16 *xh, *xl, *qh, *ql, *kh, *kl, *vh, *vl, *zh, *zl, *wth, *wtl;
    cudaGetSymbolAddress((void**)&xh, g_xh);
    cudaGetSymbolAddress((void**)&xl, g_xl);
    cudaGetSymbolAddress((void**)&qh, g_qh);
    cudaGetSymbolAddress((void**)&ql, g_ql);
    cudaGetSymbolAddress((void**)&kh, g_kh);
    cudaGetSymbolAddress((void**)&kl, g_kl);
    cudaGetSymbolAddress((void**)&vh, g_vh);
    cudaGetSymbolAddress((void**)&vl, g_vl);
    cudaGetSymbolAddress((void**)&zh, g_zh);
    cudaGetSymbolAddress((void**)&zl, g_zl);
    cudaGetSymbolAddress((void**)&wth, g_wth);
    cudaGetSymbolAddress((void**)&wtl, g_wtl);

    const int NW = D_DIM * D_DIM;

    // 1) split x; transpose+split all 4 weights in one launch
    k_split<<<(MROWS * D_DIM + 255) / 256, 256>>>(x, xh, xl, MROWS * D_DIM);
    k_tsplit4<<<dim3(D_DIM / 32, D_DIM / 32, 4), dim3(32, 8)>>>(Wq, Wk, Wv, Wout, wth, wtl);

    // 2) merged QKV projection (N=3072), 128-thread CTAs
    cudaFuncSetAttribute(gemm_mma3, cudaFuncAttributeMaxDynamicSharedMemorySize, GEMM_SMEM);
    gemm_mma3<<<dim3(3 * D_DIM / TILE_N, MROWS / TILE_M), 128, GEMM_SMEM>>>(
        xh, xl, wth, wtl, nullptr, nullptr, qh, ql, kh, kl, vh, vl);

    // 3) tensor-core flash attention (64-row CTAs, 2 CTAs/SM) -> zh/zl
    cudaFuncSetAttribute(attn_mma, cudaFuncAttributeMaxDynamicSharedMemorySize, ATT_SMEM);
    attn_mma<<<dim3(S_LEN / 64, H_NUM, B_NUM), 128, ATT_SMEM>>>(qh, ql, kh, kl, vh, vl, zh, zl);

    // 4) output projection + residual -> fp32 out
    gemm_mma3<<<dim3(D_DIM / TILE_N, MROWS / TILE_M), 128, GEMM_SMEM>>>(
        zh, zl, wth + 3 * (size_t)NW, wtl + 3 * (size_t)NW, x, out,
        nullptr, nullptr, nullptr, nullptr, nullptr, nullptr);
}

// round 13
// speedup vs baseline: 1.0333x; 1.0333x over previous
#include <cuda_runtime.h>
#include <cuda_bf16.h>
#include <stdint.h>

// Problem dims (fixed)
#define B_NUM 4
#define S_LEN 2048
#define D_DIM 1024
#define H_NUM 16
#define DH 64
#define MROWS (B_NUM * S_LEN)   // 8192

// bf16 split operands
__device__ __nv_bfloat16 g_xh[MROWS * D_DIM];
__device__ __nv_bfloat16 g_xl[MROWS * D_DIM];
__device__ __nv_bfloat16 g_qh[MROWS * D_DIM];
__device__ __nv_bfloat16 g_ql[MROWS * D_DIM];
__device__ __nv_bfloat16 g_kh[MROWS * D_DIM];
__device__ __nv_bfloat16 g_kl[MROWS * D_DIM];
__device__ __nv_bfloat16 g_vh[MROWS * D_DIM];
__device__ __nv_bfloat16 g_vl[MROWS * D_DIM];
__device__ __nv_bfloat16 g_zh[MROWS * D_DIM];
__device__ __nv_bfloat16 g_zl[MROWS * D_DIM];
// transposed weights [n][k], hi/lo, for Wq,Wk,Wv,Wout (contiguous rows 0..4095)
__device__ __nv_bfloat16 g_wth[4][D_DIM * D_DIM];
__device__ __nv_bfloat16 g_wtl[4][D_DIM * D_DIM];

// ---------------------------------------------------------------------------
// Helpers
// ---------------------------------------------------------------------------
__device__ __forceinline__ uint32_t smem_u32(const void* p) {
    uint32_t a;
    asm("{ .reg .u64 t; cvta.to.shared.u64 t, %1; cvt.u32.u64 %0, t; }" : "=r"(a) : "l"(p));
    return a;
}
#define SW128(off) ((off) ^ (((off) >> 3) & 0x70))
__device__ __forceinline__ void cpa16(uint32_t s, const void* g) {
    asm volatile("cp.async.cg.shared.global [%0], [%1], 16;" :: "r"(s), "l"(__cvta_generic_to_global(g)));
}
#define CP_COMMIT() asm volatile("cp.async.commit_group;" ::: "memory")
template <int N> __device__ __forceinline__ void cp_wait() {
    asm volatile("cp.async.wait_group %0;" :: "n"(N) : "memory");
}
__device__ __forceinline__ void ldsm4(uint32_t* r, uint32_t addr) {
    asm volatile("ldmatrix.sync.aligned.m8n8.x4.shared.b16 {%0,%1,%2,%3}, [%4];"
                 : "=r"(r[0]), "=r"(r[1]), "=r"(r[2]), "=r"(r[3]) : "r"(addr));
}
__device__ __forceinline__ void ldsm4t(uint32_t* r, uint32_t addr) {
    asm volatile("ldmatrix.sync.aligned.m8n8.x4.trans.shared.b16 {%0,%1,%2,%3}, [%4];"
                 : "=r"(r[0]), "=r"(r[1]), "=r"(r[2]), "=r"(r[3]) : "r"(addr));
}
__device__ __forceinline__ void mma_bf16(float* c, const uint32_t* a, uint32_t b0, uint32_t b1) {
    asm volatile("mma.sync.aligned.m16n8k16.row.col.f32.bf16.bf16.f32 "
                 "{%0,%1,%2,%3}, {%4,%5,%6,%7}, {%8,%9}, {%0,%1,%2,%3};"
                 : "+f"(c[0]), "+f"(c[1]), "+f"(c[2]), "+f"(c[3])
                 : "r"(a[0]), "r"(a[1]), "r"(a[2]), "r"(a[3]), "r"(b0), "r"(b1));
}
__device__ __forceinline__ void split_pack(float x0, float x1, uint32_t& hp, uint32_t& lp) {
    const uint32_t b0 = __float_as_uint(x0), b1 = __float_as_uint(x1);
    hp = __byte_perm(b0, b1, 0x7632);
    const float l0 = x0 - __uint_as_float(b0 & 0xFFFF0000u);
    const float l1 = x1 - __uint_as_float(b1 & 0xFFFF0000u);
    const __nv_bfloat162 lv = __float22bfloat162_rn(make_float2(l0, l1));
    lp = *(const uint32_t*)&lv;
}
__device__ __forceinline__ float ex2_mufu(float y) {
    float r; asm("ex2.approx.f32 %0, %1;" : "=f"(r) : "f"(y)); return r;
}

// ---------------------------------------------------------------------------
// Conversion kernels
// ---------------------------------------------------------------------------
__global__ void k_split(const float* __restrict__ x, __nv_bfloat16* __restrict__ h,
                        __nv_bfloat16* __restrict__ l, int n) {
    int i = blockIdx.x * blockDim.x + threadIdx.x;
    if (i < n) {
        const float v = x[i];
        const __nv_bfloat16 hh = __float2bfloat16(v);
        h[i] = hh;
        l[i] = __float2bfloat16(v - __bfloat162float(hh));
    }
}
__global__ void k_tsplit4(const float* __restrict__ W0, const float* __restrict__ W1,
                          const float* __restrict__ W2, const float* __restrict__ W3,
                          __nv_bfloat16* __restrict__ Th, __nv_bfloat16* __restrict__ Tl) {
    __shared__ float t[32][33];
    const int w = blockIdx.z;
    const float* W = (w == 0) ? W0 : (w == 1) ? W1 : (w == 2) ? W2 : W3;
    const size_t obase = (size_t)w * D_DIM * D_DIM;
    const int n0 = blockIdx.x * 32, k0 = blockIdx.y * 32;
    const int x = threadIdx.x, y = threadIdx.y;  // blockDim (32,8)
#pragma unroll
    for (int r = 0; r < 32; r += 8)
        t[y + r][x] = W[(size_t)(k0 + y + r) * D_DIM + n0 + x];
    __syncthreads();
#pragma unroll
    for (int r = 0; r < 32; r += 8) {
        const float v = t[x][y + r];
        const __nv_bfloat16 hh = __float2bfloat16(v);
        const size_t off = obase + (size_t)(n0 + y + r) * D_DIM + k0 + x;
        Th[off] = hh;
        Tl[off] = __float2bfloat16(v - __bfloat162float(hh));
    }
}

// ---------------------------------------------------------------------------
// mma.sync split-bf16 GEMM, 3-stage pipeline — R11 config restored verbatim
// (256 threads, 8 warps, 32x64 warp tiles; R12's 4-warp variant regressed).
// ---------------------------------------------------------------------------
#define TILE_M 128
#define TILE_N 128
#define BK 64
#define NITER (D_DIM / BK)          // 16
#define OFF_AH 0
#define OFF_AL 16384
#define OFF_BH 32768
#define OFF_BL 49152
#define STAGE_BYTES 65536
#define GEMM_SMEM (3 * STAGE_BYTES)   // 192KB

__device__ __forceinline__ void gemm_loads(
    uint32_t sbase, int tid, int kt, int m0, int n0,
    const __nv_bfloat16* Ah, const __nv_bfloat16* Al,
    const __nv_bfloat16* Bh, const __nv_bfloat16* Bl)
{
    const int k0 = kt * BK;
#pragma unroll
    for (int c = tid; c < 1024; c += 256) {
        const int row = c >> 3, kc = c & 7;
        const uint32_t sw = SW128((uint32_t)(row * 128 + kc * 16));
        const size_t ga = (size_t)(m0 + row) * D_DIM + k0 + kc * 8;
        const size_t gb = (size_t)(n0 + row) * D_DIM + k0 + kc * 8;
        cpa16(sbase + OFF_AH + sw, Ah + ga);
        cpa16(sbase + OFF_AL + sw, Al + ga);
        cpa16(sbase + OFF_BH + sw, Bh + gb);
        cpa16(sbase + OFF_BL + sw, Bl + gb);
    }
    CP_COMMIT();
}

__global__ __launch_bounds__(256, 1)
void gemm_mma3(const __nv_bfloat16* __restrict__ Ah, const __nv_bfloat16* __restrict__ Al,
               const __nv_bfloat16* __restrict__ Bh, const __nv_bfloat16* __restrict__ Bl,
               const float* __restrict__ resid, float* __restrict__ Cf,
               __nv_bfloat16* __restrict__ O0h, __nv_bfloat16* __restrict__ O0l,
               __nv_bfloat16* __restrict__ O1h, __nv_bfloat16* __restrict__ O1l,
               __nv_bfloat16* __restrict__ O2h, __nv_bfloat16* __restrict__ O2l)
{
    extern __shared__ __align__(128) char smem[];
    const uint32_t sb = smem_u32(smem);
    const int tid = threadIdx.x, wid = tid >> 5, lane = tid & 31;
    const int warp_m = wid & 3;
    const int warp_n = wid >> 2;
    const int n0 = blockIdx.x * TILE_N;
    const int m0 = blockIdx.y * TILE_M;

    float acc[2][8][4];
#pragma unroll
    for (int mt = 0; mt < 2; mt++)
#pragma unroll
        for (int nt = 0; nt < 8; nt++)
#pragma unroll
            for (int i = 0; i < 4; i++) acc[mt][nt][i] = 0.f;

    gemm_loads(sb, tid, 0, m0, n0, Ah, Al, Bh, Bl);
    gemm_loads(sb + STAGE_BYTES, tid, 1, m0, n0, Ah, Al, Bh, Bl);
    cp_wait<1>();
    __syncthreads();

    const int arow = warp_m * 32 + (lane & 15);
    const uint32_t acolb = (uint32_t)((lane >> 4) << 4);
    const int brow = warp_n * 64 + ((lane >> 4) << 3) + (lane & 7);
    const uint32_t bcolb = (uint32_t)(((lane >> 3) & 1) << 4);

    for (int it = 0; it < NITER; it++) {
        if (it + 2 < NITER)
            gemm_loads(sb + ((it + 2) % 3) * STAGE_BYTES, tid, it + 2, m0, n0, Ah, Al, Bh, Bl);

        const uint32_t s0 = sb + (it % 3) * STAGE_BYTES;
#pragma unroll
        for (int ks = 0; ks < 4; ks++) {
            const uint32_t kb = (uint32_t)(ks * 32);
            uint32_t ah[2][4], al[2][4];
#pragma unroll
            for (int mt = 0; mt < 2; mt++) {
                const uint32_t off = SW128((uint32_t)((arow + mt * 16) * 128) + kb + acolb);
                ldsm4(ah[mt], s0 + OFF_AH + off);
                ldsm4(al[mt], s0 + OFF_AL + off);
            }
            uint32_t bh[4][4], bl[4][4];
#pragma unroll
            for (int p = 0; p < 4; p++) {
                const uint32_t off = SW128((uint32_t)((brow + p * 16) * 128) + kb + bcolb);
                ldsm4(bh[p], s0 + OFF_BH + off);
                ldsm4(bl[p], s0 + OFF_BL + off);
            }
#pragma unroll
            for (int mt = 0; mt < 2; mt++)
#pragma unroll
                for (int p = 0; p < 4; p++)
#pragma unroll
                    for (int hf = 0; hf < 2; hf++) {
                        float* c = acc[mt][p * 2 + hf];
                        mma_bf16(c, ah[mt], bh[p][hf * 2], bh[p][hf * 2 + 1]);
                        mma_bf16(c, ah[mt], bl[p][hf * 2], bl[p][hf * 2 + 1]);
                        mma_bf16(c, al[mt], bh[p][hf * 2], bh[p][hf * 2 + 1]);
                    }
        }

        if (it + 2 < NITER) cp_wait<1>(); else cp_wait<0>();
        __syncthreads();
    }

    const int sel = n0 >> 10;
    const int nl = n0 & (D_DIM - 1);
    __nv_bfloat16* Oh = (sel == 0) ? O0h : (sel == 1) ? O1h : O2h;
    __nv_bfloat16* Ol = (sel == 0) ? O0l : (sel == 1) ? O1l : O2l;
#pragma unroll
    for (int mt = 0; mt < 2; mt++) {
        const int row0 = m0 + warp_m * 32 + mt * 16 + (lane >> 2);
#pragma unroll
        for (int nt = 0; nt < 8; nt++) {
            const int coll = nl + warp_n * 64 + nt * 8 + (lane & 3) * 2;
            const float* c = acc[mt][nt];
            const size_t off = (size_t)row0 * D_DIM + coll;
            if (Cf) {
                float2 v0 = make_float2(c[0], c[1]);
                float2 v1 = make_float2(c[2], c[3]);
                if (resid) {
                    const float2 r0 = *(const float2*)&resid[off];
                    const float2 r1 = *(const float2*)&resid[off + 8 * D_DIM];
                    v0.x += r0.x; v0.y += r0.y; v1.x += r1.x; v1.y += r1.y;
                }
                *(float2*)&Cf[off] = v0;
                *(float2*)&Cf[off + 8 * D_DIM] = v1;
            } else {
                uint32_t hp, lp;
                split_pack(c[0], c[1], hp, lp);
                *(uint32_t*)&Oh[off] = hp; *(uint32_t*)&Ol[off] = lp;
                split_pack(c[2], c[3], hp, lp);
                *(uint32_t*)&Oh[off + 8 * D_DIM] = hp; *(uint32_t*)&Ol[off + 8 * D_DIM] = lp;
            }
        }
    }
}

// ---------------------------------------------------------------------------
// Tensor-core flash attention. R13: staggered kv start per CTA — co-resident
// CTAs (bid, bid+148) get opposite phases ((bid>>2)&1 differs since 37 is odd)
// so one CTA's softmax overlaps the other's mma bursts instead of phase-
// locking. Full mask -> kv iteration order is irrelevant to the result.
// ---------------------------------------------------------------------------
#define ATT_SMEM (16384 + 3 * 32768)   // 114688
#define SLOG2E 0.1803368801111204f     // 0.125 * log2(e)
#define NKV (S_LEN / 64)               // 32

__device__ __forceinline__ void attn_kv_load(
    uint32_t sbase, int tid, size_t kvbase, int k0,
    const __nv_bfloat16* kh, const __nv_bfloat16* kl,
    const __nv_bfloat16* vh, const __nv_bfloat16* vl)
{
#pragma unroll
    for (int c = tid; c < 512; c += 128) {
        const int row = c >> 3, ch = c & 7;
        const uint32_t sw = SW128((uint32_t)(row * 128 + ch * 16));
        const size_t g = kvbase + (size_t)(k0 + row) * D_DIM + ch * 8;
        cpa16(sbase + sw, kh + g);
        cpa16(sbase + 8192 + sw, kl + g);
        cpa16(sbase + 16384 + sw, vh + g);
        cpa16(sbase + 24576 + sw, vl + g);
    }
    CP_COMMIT();
}

__global__ __launch_bounds__(128, 2)
void attn_mma(const __nv_bfloat16* __restrict__ qh, const __nv_bfloat16* __restrict__ ql,
              const __nv_bfloat16* __restrict__ kh, const __nv_bfloat16* __restrict__ kl,
              const __nv_bfloat16* __restrict__ vh, const __nv_bfloat16* __restrict__ vl,
              __nv_bfloat16* __restrict__ zh, __nv_bfloat16* __restrict__ zl)
{
    extern __shared__ __align__(128) char smem[];
    const uint32_t sb = smem_u32(smem);
    const int tid = threadIdx.x, wid = tid >> 5, lane = tid & 31;
    const int q0 = blockIdx.x * 64;
    const int h = blockIdx.y, b = blockIdx.z;
    const size_t qbase = ((size_t)(b * S_LEN + q0)) * D_DIM + h * DH;
    const size_t kvbase = ((size_t)b * S_LEN) * D_DIM + h * DH;
    // Anti-phase stagger: co-resident CTAs differ in (bid>>2)&1
    const int phase = ((blockIdx.x >> 2) & 1) * (NKV / 2);

#pragma unroll
    for (int c = tid; c < 512; c += 128) {
        const int row = c >> 3, ch = c & 7;
        const uint32_t sw = SW128((uint32_t)(row * 128 + ch * 16));
        const size_t g = qbase + (size_t)row * D_DIM + ch * 8;
        cpa16(sb + sw, qh + g);
        cpa16(sb + 8192 + sw, ql + g);
    }
    CP_COMMIT();
    attn_kv_load(sb + 16384, tid, kvbase, (phase & (NKV - 1)) * 64, kh, kl, vh, vl);
    attn_kv_load(sb + 16384 + 32768, tid, kvbase, ((phase + 1) & (NKV - 1)) * 64, kh, kl, vh, vl);
    cp_wait<1>();
    __syncthreads();

    const int arow = wid * 16 + (lane & 15);
    const uint32_t acolb = (uint32_t)((lane >> 4) << 4);
    const int bnrow = ((lane >> 4) << 3) + (lane & 7);
    const uint32_t bncol = (uint32_t)(((lane >> 3) & 1) << 4);
    const int vrow = ((lane >> 3) & 1) * 8 + (lane & 7);
    const uint32_t vcolb = (uint32_t)((lane >> 4) << 4);

    uint32_t qfh[4][4], qfl[4][4];
#pragma unroll
    for (int ks = 0; ks < 4; ks++) {
        const uint32_t off = SW128((uint32_t)(arow * 128) + (uint32_t)(ks * 32) + acolb);
        ldsm4(qfh[ks], sb + off);
        ldsm4(qfl[ks], sb + 8192 + off);
    }

    float O[8][4];
#pragma unroll
    for (int nt = 0; nt < 8; nt++)
#pragma unroll
        for (int i = 0; i < 4; i++) O[nt][i] = 0.f;
    float m0 = -1.0e30f, m1 = -1.0e30f, l0 = 0.f, l1 = 0.f;

    for (int tt = 0; tt < NKV; tt++) {
        if (tt + 2 < NKV)
            attn_kv_load(sb + 16384 + ((tt + 2) % 3) * 32768, tid, kvbase,
                         ((tt + 2 + phase) & (NKV - 1)) * 64, kh, kl, vh, vl);

        const uint32_t kbB = sb + 16384 + (tt % 3) * 32768;

        float S[8][4];
#pragma unroll
        for (int nt = 0; nt < 8; nt++)
#pragma unroll
            for (int i = 0; i < 4; i++) S[nt][i] = 0.f;
#pragma unroll
        for (int ks = 0; ks < 4; ks++) {
            uint32_t bh_[4][4], bl_[4][4];
#pragma unroll
            for (int p = 0; p < 4; p++) {
                const uint32_t off = SW128((uint32_t)((p * 16 + bnrow) * 128) + (uint32_t)(ks * 32) + bncol);
                ldsm4(bh_[p], kbB + off);
                ldsm4(bl_[p], kbB + 8192 + off);
            }
#pragma unroll
            for (int p = 0; p < 4; p++)
#pragma unroll
                for (int hf = 0; hf < 2; hf++) {
                    float* c = S[p * 2 + hf];
                    mma_bf16(c, qfh[ks], bh_[p][hf * 2], bh_[p][hf * 2 + 1]);
                    mma_bf16(c, qfh[ks], bl_[p][hf * 2], bl_[p][hf * 2 + 1]);
                    mma_bf16(c, qfl[ks], bh_[p][hf * 2], bh_[p][hf * 2 + 1]);
                }
        }

        float mx0 = -1.0e30f, mx1 = -1.0e30f;
#pragma unroll
        for (int nt = 0; nt < 8; nt++) {
            mx0 = fmaxf(mx0, fmaxf(S[nt][0], S[nt][1]));
            mx1 = fmaxf(mx1, fmaxf(S[nt][2], S[nt][3]));
        }
        mx0 = fmaxf(mx0, __shfl_xor_sync(0xffffffffu, mx0, 1));
        mx0 = fmaxf(mx0, __shfl_xor_sync(0xffffffffu, mx0, 2));
        mx1 = fmaxf(mx1, __shfl_xor_sync(0xffffffffu, mx1, 1));
        mx1 = fmaxf(mx1, __shfl_xor_sync(0xffffffffu, mx1, 2));
        const float mn0 = fmaxf(m0, mx0), mn1 = fmaxf(m1, mx1);
        const float mb0 = mn0 * SLOG2E, mb1 = mn1 * SLOG2E;
        const float a0 = ex2_mufu(fmaf(m0, SLOG2E, -mb0));
        const float a1 = ex2_mufu(fmaf(m1, SLOG2E, -mb1));
        m0 = mn0; m1 = mn1;

        float s0 = 0.f, s1 = 0.f;
#pragma unroll
        for (int nt = 0; nt < 8; nt++) {
            S[nt][0] = ex2_mufu(fmaf(S[nt][0], SLOG2E, -mb0));
            S[nt][1] = ex2_mufu(fmaf(S[nt][1], SLOG2E, -mb0));
            S[nt][2] = ex2_mufu(fmaf(S[nt][2], SLOG2E, -mb1));
            S[nt][3] = ex2_mufu(fmaf(S[nt][3], SLOG2E, -mb1));
            s0 += S[nt][0] + S[nt][1];
            s1 += S[nt][2] + S[nt][3];
        }
        l0 = l0 * a0 + s0;
        l1 = l1 * a1 + s1;

        if (__ballot_sync(0xffffffffu, (a0 != 1.0f) || (a1 != 1.0f))) {
#pragma unroll
            for (int nt = 0; nt < 8; nt++) {
                O[nt][0] *= a0; O[nt][1] *= a0; O[nt][2] *= a1; O[nt][3] *= a1;
            }
        }

        uint32_t pfh[4][4], pfl[4][4];
#pragma unroll
        for (int ks = 0; ks < 4; ks++) {
            split_pack(S[2 * ks][0], S[2 * ks][1], pfh[ks][0], pfl[ks][0]);
            split_pack(S[2 * ks][2], S[2 * ks][3], pfh[ks][1], pfl[ks][1]);
            split_pack(S[2 * ks + 1][0], S[2 * ks + 1][1], pfh[ks][2], pfl[ks][2]);
            split_pack(S[2 * ks + 1][2], S[2 * ks + 1][3], pfh[ks][3], pfl[ks][3]);
        }

#pragma unroll
        for (int ks = 0; ks < 4; ks++) {
            uint32_t vh_[4][4], vl_[4][4];
#pragma unroll
            for (int p = 0; p < 4; p++) {
                const uint32_t off = SW128((uint32_t)((ks * 16 + vrow) * 128) + (uint32_t)(p * 32) + vcolb);
                ldsm4t(vh_[p], kbB + 16384 + off);
                ldsm4t(vl_[p], kbB + 24576 + off);
            }
#pragma unroll
            for (int p = 0; p < 4; p++)
#pragma unroll
                for (int hf = 0; hf < 2; hf++) {
                    float* o = O[p * 2 + hf];
                    mma_bf16(o, pfh[ks], vh_[p][hf * 2], vh_[p][hf * 2 + 1]);
                    mma_bf16(o, pfh[ks], vl_[p][hf * 2], vl_[p][hf * 2 + 1]);
                    mma_bf16(o, pfl[ks], vh_[p][hf * 2], vh_[p][hf * 2 + 1]);
                }
        }

        if (tt + 2 < NKV) cp_wait<1>(); else cp_wait<0>();
        __syncthreads();
    }

    l0 += __shfl_xor_sync(0xffffffffu, l0, 1);
    l0 += __shfl_xor_sync(0xffffffffu, l0, 2);
    l1 += __shfl_xor_sync(0xffffffffu, l1, 1);
    l1 += __shfl_xor_sync(0xffffffffu, l1, 2);
    const float inv0 = 1.0f / l0, inv1 = 1.0f / l1;

    const int rowg = b * S_LEN + q0 + wid * 16 + (lane >> 2);
#pragma unroll
    for (int nt = 0; nt < 8; nt++) {
        const int col = h * DH + nt * 8 + (lane & 3) * 2;
        uint32_t hp, lp;
        split_pack(O[nt][0] * inv0, O[nt][1] * inv0, hp, lp);
        size_t off = (size_t)rowg * D_DIM + col;
        *(uint32_t*)&zh[off] = hp; *(uint32_t*)&zl[off] = lp;
        split_pack(O[nt][2] * inv1, O[nt][3] * inv1, hp, lp);
        off += (size_t)8 * D_DIM;
        *(uint32_t*)&zh[off] = hp; *(uint32_t*)&zl[off] = lp;
    }
}

// ---------------------------------------------------------------------------
// Inputs (metadata order): x, mask(bool, unused), Wq, Wk, Wv, Wout
// ---------------------------------------------------------------------------
extern "C" void kernel_launch(void* const* d_in, const int* in_sizes, int n_in,
                              void* d_out, int out_size)
{
    (void)in_sizes; (void)n_in; (void)out_size;
    const float* x    = (const float*)d_in[0];
    const float* Wq   = (const float*)d_in[2];
    const float* Wk   = (const float*)d_in[3];
    const float* Wv   = (const float*)d_in[4];
    const float* Wout = (const float*)d_in[5];
    float* out = (float*)d_out;

    __nv_bfloat16 *xh, *xl, *qh, *ql, *kh, *kl, *vh, *vl, *zh, *zl, *wth, *wtl;
    cudaGetSymbolAddress((void**)&xh, g_xh);
    cudaGetSymbolAddress((void**)&xl, g_xl);
    cudaGetSymbolAddress((void**)&qh, g_qh);
    cudaGetSymbolAddress((void**)&ql, g_ql);
    cudaGetSymbolAddress((void**)&kh, g_kh);
    cudaGetSymbolAddress((void**)&kl, g_kl);
    cudaGetSymbolAddress((void**)&vh, g_vh);
    cudaGetSymbolAddress((void**)&vl, g_vl);
    cudaGetSymbolAddress((void**)&zh, g_zh);
    cudaGetSymbolAddress((void**)&zl, g_zl);
    cudaGetSymbolAddress((void**)&wth, g_wth);
    cudaGetSymbolAddress((void**)&wtl, g_wtl);

    const int NW = D_DIM * D_DIM;

    // 1) split x; transpose+split all 4 weights in one launch
    k_split<<<(MROWS * D_DIM + 255) / 256, 256>>>(x, xh, xl, MROWS * D_DIM);
    k_tsplit4<<<dim3(D_DIM / 32, D_DIM / 32, 4), dim3(32, 8)>>>(Wq, Wk, Wv, Wout, wth, wtl);

    // 2) merged QKV projection (N=3072), 256-thread CTAs (R11 config)
    cudaFuncSetAttribute(gemm_mma3, cudaFuncAttributeMaxDynamicSharedMemorySize, GEMM_SMEM);
    gemm_mma3<<<dim3(3 * D_DIM / TILE_N, MROWS / TILE_M), 256, GEMM_SMEM>>>(
        xh, xl, wth, wtl, nullptr, nullptr, qh, ql, kh, kl, vh, vl);

    // 3) tensor-core flash attention (64-row CTAs, 2 CTAs/SM, kv-staggered)
    cudaFuncSetAttribute(attn_mma, cudaFuncAttributeMaxDynamicSharedMemorySize, ATT_SMEM);
    attn_mma<<<dim3(S_LEN / 64, H_NUM, B_NUM), 128, ATT_SMEM>>>(qh, ql, kh, kl, vh, vl, zh, zl);

    // 4) output projection + residual -> fp32 out
    gemm_mma3<<<dim3(D_DIM / TILE_N, MROWS / TILE_M), 256, GEMM_SMEM>>>(
        zh, zl, wth + 3 * (size_t)NW, wtl + 3 * (size_t)NW, x, out,
        nullptr, nullptr, nullptr, nullptr, nullptr, nullptr);
}

// round 14
// speedup vs baseline: 1.4554x; 1.4086x over previous
#include <cuda_runtime.h>
#include <cuda_fp16.h>
#include <stdint.h>

// Problem dims (fixed)
#define B_NUM 4
#define S_LEN 2048
#define D_DIM 1024
#define H_NUM 16
#define DH 64
#define MROWS (B_NUM * S_LEN)   // 8192

// fp16 operands: A-side 2-term (hi+lo), B-side hi-only
__device__ __half g_xh[MROWS * D_DIM];
__device__ __half g_xl[MROWS * D_DIM];
__device__ __half g_qh[MROWS * D_DIM];
__device__ __half g_ql[MROWS * D_DIM];
__device__ __half g_kh[MROWS * D_DIM];   // hi only (B operand of QK)
__device__ __half g_vh[MROWS * D_DIM];   // hi only (B operand of PV)
__device__ __half g_zh[MROWS * D_DIM];
__device__ __half g_zl[MROWS * D_DIM];
// transposed weights [n][k], hi only, for Wq,Wk,Wv,Wout (contiguous rows 0..4095)
__device__ __half g_wth[4][D_DIM * D_DIM];

// ---------------------------------------------------------------------------
// Helpers
// ---------------------------------------------------------------------------
__device__ __forceinline__ uint32_t smem_u32(const void* p) {
    uint32_t a;
    asm("{ .reg .u64 t; cvta.to.shared.u64 t, %1; cvt.u32.u64 %0, t; }" : "=r"(a) : "l"(p));
    return a;
}
#define SW128(off) ((off) ^ (((off) >> 3) & 0x70))
__device__ __forceinline__ void cpa16(uint32_t s, const void* g) {
    asm volatile("cp.async.cg.shared.global [%0], [%1], 16;" :: "r"(s), "l"(__cvta_generic_to_global(g)));
}
#define CP_COMMIT() asm volatile("cp.async.commit_group;" ::: "memory")
template <int N> __device__ __forceinline__ void cp_wait() {
    asm volatile("cp.async.wait_group %0;" :: "n"(N) : "memory");
}
__device__ __forceinline__ void ldsm4(uint32_t* r, uint32_t addr) {
    asm volatile("ldmatrix.sync.aligned.m8n8.x4.shared.b16 {%0,%1,%2,%3}, [%4];"
                 : "=r"(r[0]), "=r"(r[1]), "=r"(r[2]), "=r"(r[3]) : "r"(addr));
}
__device__ __forceinline__ void ldsm4t(uint32_t* r, uint32_t addr) {
    asm volatile("ldmatrix.sync.aligned.m8n8.x4.trans.shared.b16 {%0,%1,%2,%3}, [%4];"
                 : "=r"(r[0]), "=r"(r[1]), "=r"(r[2]), "=r"(r[3]) : "r"(addr));
}
__device__ __forceinline__ void mma_f16(float* c, const uint32_t* a, uint32_t b0, uint32_t b1) {
    asm volatile("mma.sync.aligned.m16n8k16.row.col.f32.f16.f16.f32 "
                 "{%0,%1,%2,%3}, {%4,%5,%6,%7}, {%8,%9}, {%0,%1,%2,%3};"
                 : "+f"(c[0]), "+f"(c[1]), "+f"(c[2]), "+f"(c[3])
                 : "r"(a[0]), "r"(a[1]), "r"(a[2]), "r"(a[3]), "r"(b0), "r"(b1));
}
// fp16 split: hi = RN(x), lo = RN(x - hi); packed as half2
__device__ __forceinline__ void split_pack_f16(float x0, float x1, uint32_t& hp, uint32_t& lp) {
    const __half2 h2 = __floats2half2_rn(x0, x1);
    hp = *(const uint32_t*)&h2;
    const float l0 = x0 - __low2float(h2);
    const float l1 = x1 - __high2float(h2);
    const __half2 l2 = __floats2half2_rn(l0, l1);
    lp = *(const uint32_t*)&l2;
}
__device__ __forceinline__ float ex2_mufu(float y) {
    float r; asm("ex2.approx.f32 %0, %1;" : "=f"(r) : "f"(y)); return r;
}

// ---------------------------------------------------------------------------
// Conversion kernels
// ---------------------------------------------------------------------------
__global__ void k_split(const float* __restrict__ x, __half* __restrict__ h,
                        __half* __restrict__ l, int n) {
    int i = blockIdx.x * blockDim.x + threadIdx.x;
    if (i < n) {
        const float v = x[i];
        const __half hh = __float2half_rn(v);
        h[i] = hh;
        l[i] = __float2half_rn(v - __half2float(hh));
    }
}
// All four weights, hi-only transposed output
__global__ void k_tsplit4(const float* __restrict__ W0, const float* __restrict__ W1,
                          const float* __restrict__ W2, const float* __restrict__ W3,
                          __half* __restrict__ Th) {
    __shared__ float t[32][33];
    const int w = blockIdx.z;
    const float* W = (w == 0) ? W0 : (w == 1) ? W1 : (w == 2) ? W2 : W3;
    const size_t obase = (size_t)w * D_DIM * D_DIM;
    const int n0 = blockIdx.x * 32, k0 = blockIdx.y * 32;
    const int x = threadIdx.x, y = threadIdx.y;  // blockDim (32,8)
#pragma unroll
    for (int r = 0; r < 32; r += 8)
        t[y + r][x] = W[(size_t)(k0 + y + r) * D_DIM + n0 + x];
    __syncthreads();
#pragma unroll
    for (int r = 0; r < 32; r += 8) {
        const float v = t[x][y + r];
        Th[obase + (size_t)(n0 + y + r) * D_DIM + k0 + x] = __float2half_rn(v);
    }
}

// ---------------------------------------------------------------------------
// mma.sync fp16 2-term GEMM: C = (Ah+Al) @ Bh^T, 3-stage pipeline,
// 256 threads / 8 warps / 32x64 warp tiles (R11-validated config).
// ---------------------------------------------------------------------------
#define TILE_M 128
#define TILE_N 128
#define BK 64
#define NITER (D_DIM / BK)          // 16
#define OFF_AH 0
#define OFF_AL 16384
#define OFF_BH 32768
#define STAGE_BYTES 49152           // 48KB
#define GEMM_SMEM (3 * STAGE_BYTES) // 144KB

__device__ __forceinline__ void gemm_loads(
    uint32_t sbase, int tid, int kt, int m0, int n0,
    const __half* Ah, const __half* Al, const __half* Bh)
{
    const int k0 = kt * BK;
#pragma unroll
    for (int c = tid; c < 1024; c += 256) {
        const int row = c >> 3, kc = c & 7;
        const uint32_t sw = SW128((uint32_t)(row * 128 + kc * 16));
        const size_t ga = (size_t)(m0 + row) * D_DIM + k0 + kc * 8;
        const size_t gb = (size_t)(n0 + row) * D_DIM + k0 + kc * 8;
        cpa16(sbase + OFF_AH + sw, Ah + ga);
        cpa16(sbase + OFF_AL + sw, Al + ga);
        cpa16(sbase + OFF_BH + sw, Bh + gb);
    }
    CP_COMMIT();
}

__global__ __launch_bounds__(256, 1)
void gemm_f16x2(const __half* __restrict__ Ah, const __half* __restrict__ Al,
                const __half* __restrict__ Bh,
                const float* __restrict__ resid, float* __restrict__ Cf,
                __half* __restrict__ O0h, __half* __restrict__ O0l,
                __half* __restrict__ O1h, __half* __restrict__ O2h)
{
    extern __shared__ __align__(128) char smem[];
    const uint32_t sb = smem_u32(smem);
    const int tid = threadIdx.x, wid = tid >> 5, lane = tid & 31;
    const int warp_m = wid & 3;
    const int warp_n = wid >> 2;
    const int n0 = blockIdx.x * TILE_N;
    const int m0 = blockIdx.y * TILE_M;

    float acc[2][8][4];
#pragma unroll
    for (int mt = 0; mt < 2; mt++)
#pragma unroll
        for (int nt = 0; nt < 8; nt++)
#pragma unroll
            for (int i = 0; i < 4; i++) acc[mt][nt][i] = 0.f;

    gemm_loads(sb, tid, 0, m0, n0, Ah, Al, Bh);
    gemm_loads(sb + STAGE_BYTES, tid, 1, m0, n0, Ah, Al, Bh);
    cp_wait<1>();
    __syncthreads();

    const int arow = warp_m * 32 + (lane & 15);
    const uint32_t acolb = (uint32_t)((lane >> 4) << 4);
    const int brow = warp_n * 64 + ((lane >> 4) << 3) + (lane & 7);
    const uint32_t bcolb = (uint32_t)(((lane >> 3) & 1) << 4);

    for (int it = 0; it < NITER; it++) {
        if (it + 2 < NITER)
            gemm_loads(sb + ((it + 2) % 3) * STAGE_BYTES, tid, it + 2, m0, n0, Ah, Al, Bh);

        const uint32_t s0 = sb + (it % 3) * STAGE_BYTES;
#pragma unroll
        for (int ks = 0; ks < 4; ks++) {
            const uint32_t kb = (uint32_t)(ks * 32);
            uint32_t ah[2][4], al[2][4];
#pragma unroll
            for (int mt = 0; mt < 2; mt++) {
                const uint32_t off = SW128((uint32_t)((arow + mt * 16) * 128) + kb + acolb);
                ldsm4(ah[mt], s0 + OFF_AH + off);
                ldsm4(al[mt], s0 + OFF_AL + off);
            }
            uint32_t bh[4][4];
#pragma unroll
            for (int p = 0; p < 4; p++) {
                const uint32_t off = SW128((uint32_t)((brow + p * 16) * 128) + kb + bcolb);
                ldsm4(bh[p], s0 + OFF_BH + off);
            }
#pragma unroll
            for (int mt = 0; mt < 2; mt++)
#pragma unroll
                for (int p = 0; p < 4; p++)
#pragma unroll
                    for (int hf = 0; hf < 2; hf++) {
                        float* c = acc[mt][p * 2 + hf];
                        mma_f16(c, ah[mt], bh[p][hf * 2], bh[p][hf * 2 + 1]);
                        mma_f16(c, al[mt], bh[p][hf * 2], bh[p][hf * 2 + 1]);
                    }
        }

        if (it + 2 < NITER) cp_wait<1>(); else cp_wait<0>();
        __syncthreads();
    }

    // epilogue: fp32 (+resid) or fp16 split/hi outputs routed by n0>>10
    const int sel = n0 >> 10;
    const int nl = n0 & (D_DIM - 1);
    __half* Oh = (sel == 0) ? O0h : (sel == 1) ? O1h : O2h;
    __half* Ol = (sel == 0) ? O0l : (__half*)0;
#pragma unroll
    for (int mt = 0; mt < 2; mt++) {
        const int row0 = m0 + warp_m * 32 + mt * 16 + (lane >> 2);
#pragma unroll
        for (int nt = 0; nt < 8; nt++) {
            const int coll = nl + warp_n * 64 + nt * 8 + (lane & 3) * 2;
            const float* c = acc[mt][nt];
            const size_t off = (size_t)row0 * D_DIM + coll;
            if (Cf) {
                float2 v0 = make_float2(c[0], c[1]);
                float2 v1 = make_float2(c[2], c[3]);
                if (resid) {
                    const float2 r0 = *(const float2*)&resid[off];
                    const float2 r1 = *(const float2*)&resid[off + 8 * D_DIM];
                    v0.x += r0.x; v0.y += r0.y; v1.x += r1.x; v1.y += r1.y;
                }
                *(float2*)&Cf[off] = v0;
                *(float2*)&Cf[off + 8 * D_DIM] = v1;
            } else {
                uint32_t hp, lp;
                split_pack_f16(c[0], c[1], hp, lp);
                *(uint32_t*)&Oh[off] = hp;
                if (Ol) *(uint32_t*)&Ol[off] = lp;
                split_pack_f16(c[2], c[3], hp, lp);
                *(uint32_t*)&Oh[off + 8 * D_DIM] = hp;
                if (Ol) *(uint32_t*)&Ol[off + 8 * D_DIM] = lp;
            }
        }
    }
}

// ---------------------------------------------------------------------------
// Tensor-core flash attention, fp16 2-term (Q,P split; K,V hi-only).
// 64 q-rows / 128 threads / 4 warps per CTA, 2 CTAs/SM, kv-staggered (R13).
// smem: Qh 8K | Ql 8K | 3 stages x {Kh 8K, Vh 8K} = 64KB.
// ---------------------------------------------------------------------------
#define ATT_SMEM (16384 + 3 * 16384)   // 65536
#define SLOG2E 0.1803368801111204f     // 0.125 * log2(e)
#define NKV (S_LEN / 64)               // 32

__device__ __forceinline__ void attn_kv_load(
    uint32_t sbase, int tid, size_t kvbase, int k0,
    const __half* kh, const __half* vh)
{
#pragma unroll
    for (int c = tid; c < 512; c += 128) {
        const int row = c >> 3, ch = c & 7;
        const uint32_t sw = SW128((uint32_t)(row * 128 + ch * 16));
        const size_t g = kvbase + (size_t)(k0 + row) * D_DIM + ch * 8;
        cpa16(sbase + sw, kh + g);
        cpa16(sbase + 8192 + sw, vh + g);
    }
    CP_COMMIT();
}

__global__ __launch_bounds__(128, 2)
void attn_mma(const __half* __restrict__ qh, const __half* __restrict__ ql,
              const __half* __restrict__ kh, const __half* __restrict__ vh,
              __half* __restrict__ zh, __half* __restrict__ zl)
{
    extern __shared__ __align__(128) char smem[];
    const uint32_t sb = smem_u32(smem);
    const int tid = threadIdx.x, wid = tid >> 5, lane = tid & 31;
    const int q0 = blockIdx.x * 64;
    const int h = blockIdx.y, b = blockIdx.z;
    const size_t qbase = ((size_t)(b * S_LEN + q0)) * D_DIM + h * DH;
    const size_t kvbase = ((size_t)b * S_LEN) * D_DIM + h * DH;
    const int phase = ((blockIdx.x >> 2) & 1) * (NKV / 2);

#pragma unroll
    for (int c = tid; c < 512; c += 128) {
        const int row = c >> 3, ch = c & 7;
        const uint32_t sw = SW128((uint32_t)(row * 128 + ch * 16));
        const size_t g = qbase + (size_t)row * D_DIM + ch * 8;
        cpa16(sb + sw, qh + g);
        cpa16(sb + 8192 + sw, ql + g);
    }
    CP_COMMIT();
    attn_kv_load(sb + 16384, tid, kvbase, (phase & (NKV - 1)) * 64, kh, vh);
    attn_kv_load(sb + 16384 + 16384, tid, kvbase, ((phase + 1) & (NKV - 1)) * 64, kh, vh);
    cp_wait<1>();
    __syncthreads();

    const int arow = wid * 16 + (lane & 15);
    const uint32_t acolb = (uint32_t)((lane >> 4) << 4);
    const int bnrow = ((lane >> 4) << 3) + (lane & 7);
    const uint32_t bncol = (uint32_t)(((lane >> 3) & 1) << 4);
    const int vrow = ((lane >> 3) & 1) * 8 + (lane & 7);
    const uint32_t vcolb = (uint32_t)((lane >> 4) << 4);

    uint32_t qfh[4][4], qfl[4][4];
#pragma unroll
    for (int ks = 0; ks < 4; ks++) {
        const uint32_t off = SW128((uint32_t)(arow * 128) + (uint32_t)(ks * 32) + acolb);
        ldsm4(qfh[ks], sb + off);
        ldsm4(qfl[ks], sb + 8192 + off);
    }

    float O[8][4];
#pragma unroll
    for (int nt = 0; nt < 8; nt++)
#pragma unroll
        for (int i = 0; i < 4; i++) O[nt][i] = 0.f;
    float m0 = -1.0e30f, m1 = -1.0e30f, l0 = 0.f, l1 = 0.f;

    for (int tt = 0; tt < NKV; tt++) {
        if (tt + 2 < NKV)
            attn_kv_load(sb + 16384 + ((tt + 2) % 3) * 16384, tid, kvbase,
                         ((tt + 2 + phase) & (NKV - 1)) * 64, kh, vh);

        const uint32_t kbB = sb + 16384 + (tt % 3) * 16384;

        // ---- S = (Qh+Ql) Kh^T (2-mma), fp32 accum
        float S[8][4];
#pragma unroll
        for (int nt = 0; nt < 8; nt++)
#pragma unroll
            for (int i = 0; i < 4; i++) S[nt][i] = 0.f;
#pragma unroll
        for (int ks = 0; ks < 4; ks++) {
            uint32_t bh_[4][4];
#pragma unroll
            for (int p = 0; p < 4; p++) {
                const uint32_t off = SW128((uint32_t)((p * 16 + bnrow) * 128) + (uint32_t)(ks * 32) + bncol);
                ldsm4(bh_[p], kbB + off);
            }
#pragma unroll
            for (int p = 0; p < 4; p++)
#pragma unroll
                for (int hf = 0; hf < 2; hf++) {
                    float* c = S[p * 2 + hf];
                    mma_f16(c, qfh[ks], bh_[p][hf * 2], bh_[p][hf * 2 + 1]);
                    mma_f16(c, qfl[ks], bh_[p][hf * 2], bh_[p][hf * 2 + 1]);
                }
        }

        // ---- online softmax (all-MUFU; scale folded into exp arg)
        float mx0 = -1.0e30f, mx1 = -1.0e30f;
#pragma unroll
        for (int nt = 0; nt < 8; nt++) {
            mx0 = fmaxf(mx0, fmaxf(S[nt][0], S[nt][1]));
            mx1 = fmaxf(mx1, fmaxf(S[nt][2], S[nt][3]));
        }
        mx0 = fmaxf(mx0, __shfl_xor_sync(0xffffffffu, mx0, 1));
        mx0 = fmaxf(mx0, __shfl_xor_sync(0xffffffffu, mx0, 2));
        mx1 = fmaxf(mx1, __shfl_xor_sync(0xffffffffu, mx1, 1));
        mx1 = fmaxf(mx1, __shfl_xor_sync(0xffffffffu, mx1, 2));
        const float mn0 = fmaxf(m0, mx0), mn1 = fmaxf(m1, mx1);
        const float mb0 = mn0 * SLOG2E, mb1 = mn1 * SLOG2E;
        const float a0 = ex2_mufu(fmaf(m0, SLOG2E, -mb0));
        const float a1 = ex2_mufu(fmaf(m1, SLOG2E, -mb1));
        m0 = mn0; m1 = mn1;

        float s0 = 0.f, s1 = 0.f;
#pragma unroll
        for (int nt = 0; nt < 8; nt++) {
            S[nt][0] = ex2_mufu(fmaf(S[nt][0], SLOG2E, -mb0));
            S[nt][1] = ex2_mufu(fmaf(S[nt][1], SLOG2E, -mb0));
            S[nt][2] = ex2_mufu(fmaf(S[nt][2], SLOG2E, -mb1));
            S[nt][3] = ex2_mufu(fmaf(S[nt][3], SLOG2E, -mb1));
            s0 += S[nt][0] + S[nt][1];
            s1 += S[nt][2] + S[nt][3];
        }
        l0 = l0 * a0 + s0;
        l1 = l1 * a1 + s1;

        if (__ballot_sync(0xffffffffu, (a0 != 1.0f) || (a1 != 1.0f))) {
#pragma unroll
            for (int nt = 0; nt < 8; nt++) {
                O[nt][0] *= a0; O[nt][1] *= a0; O[nt][2] *= a1; O[nt][3] *= a1;
            }
        }

        // ---- P fragments (hi+lo) in registers
        uint32_t pfh[4][4], pfl[4][4];
#pragma unroll
        for (int ks = 0; ks < 4; ks++) {
            split_pack_f16(S[2 * ks][0], S[2 * ks][1], pfh[ks][0], pfl[ks][0]);
            split_pack_f16(S[2 * ks][2], S[2 * ks][3], pfh[ks][1], pfl[ks][1]);
            split_pack_f16(S[2 * ks + 1][0], S[2 * ks + 1][1], pfh[ks][2], pfl[ks][2]);
            split_pack_f16(S[2 * ks + 1][2], S[2 * ks + 1][3], pfh[ks][3], pfl[ks][3]);
        }

        // ---- O += (Ph+Pl) Vh (2-mma); V^T fragments via ldmatrix.trans
#pragma unroll
        for (int ks = 0; ks < 4; ks++) {
            uint32_t vh_[4][4];
#pragma unroll
            for (int p = 0; p < 4; p++) {
                const uint32_t off = SW128((uint32_t)((ks * 16 + vrow) * 128) + (uint32_t)(p * 32) + vcolb);
                ldsm4t(vh_[p], kbB + 8192 + off);
            }
#pragma unroll
            for (int p = 0; p < 4; p++)
#pragma unroll
                for (int hf = 0; hf < 2; hf++) {
                    float* o = O[p * 2 + hf];
                    mma_f16(o, pfh[ks], vh_[p][hf * 2], vh_[p][hf * 2 + 1]);
                    mma_f16(o, pfl[ks], vh_[p][hf * 2], vh_[p][hf * 2 + 1]);
                }
        }

        if (tt + 2 < NKV) cp_wait<1>(); else cp_wait<0>();
        __syncthreads();
    }

    l0 += __shfl_xor_sync(0xffffffffu, l0, 1);
    l0 += __shfl_xor_sync(0xffffffffu, l0, 2);
    l1 += __shfl_xor_sync(0xffffffffu, l1, 1);
    l1 += __shfl_xor_sync(0xffffffffu, l1, 2);
    const float inv0 = 1.0f / l0, inv1 = 1.0f / l1;

    const int rowg = b * S_LEN + q0 + wid * 16 + (lane >> 2);
#pragma unroll
    for (int nt = 0; nt < 8; nt++) {
        const int col = h * DH + nt * 8 + (lane & 3) * 2;
        uint32_t hp, lp;
        split_pack_f16(O[nt][0] * inv0, O[nt][1] * inv0, hp, lp);
        size_t off = (size_t)rowg * D_DIM + col;
        *(uint32_t*)&zh[off] = hp; *(uint32_t*)&zl[off] = lp;
        split_pack_f16(O[nt][2] * inv1, O[nt][3] * inv1, hp, lp);
        off += (size_t)8 * D_DIM;
        *(uint32_t*)&zh[off] = hp; *(uint32_t*)&zl[off] = lp;
    }
}

// ---------------------------------------------------------------------------
// Inputs (metadata order): x, mask(bool, unused), Wq, Wk, Wv, Wout
// ---------------------------------------------------------------------------
extern "C" void kernel_launch(void* const* d_in, const int* in_sizes, int n_in,
                              void* d_out, int out_size)
{
    (void)in_sizes; (void)n_in; (void)out_size;
    const float* x    = (const float*)d_in[0];
    const float* Wq   = (const float*)d_in[2];
    const float* Wk   = (const float*)d_in[3];
    const float* Wv   = (const float*)d_in[4];
    const float* Wout = (const float*)d_in[5];
    float* out = (float*)d_out;

    __half *xh, *xl, *qh, *ql, *kh, *vh, *zh, *zl, *wth;
    cudaGetSymbolAddress((void**)&xh, g_xh);
    cudaGetSymbolAddress((void**)&xl, g_xl);
    cudaGetSymbolAddress((void**)&qh, g_qh);
    cudaGetSymbolAddress((void**)&ql, g_ql);
    cudaGetSymbolAddress((void**)&kh, g_kh);
    cudaGetSymbolAddress((void**)&vh, g_vh);
    cudaGetSymbolAddress((void**)&zh, g_zh);
    cudaGetSymbolAddress((void**)&zl, g_zl);
    cudaGetSymbolAddress((void**)&wth, g_wth);

    const int NW = D_DIM * D_DIM;

    // 1) split x (hi+lo); transpose weights hi-only
    k_split<<<(MROWS * D_DIM + 255) / 256, 256>>>(x, xh, xl, MROWS * D_DIM);
    k_tsplit4<<<dim3(D_DIM / 32, D_DIM / 32, 4), dim3(32, 8)>>>(Wq, Wk, Wv, Wout, wth);

    // 2) merged QKV projection (N=3072): Q -> hi+lo, K/V -> hi only
    cudaFuncSetAttribute(gemm_f16x2, cudaFuncAttributeMaxDynamicSharedMemorySize, GEMM_SMEM);
    gemm_f16x2<<<dim3(3 * D_DIM / TILE_N, MROWS / TILE_M), 256, GEMM_SMEM>>>(
        xh, xl, wth, nullptr, nullptr, qh, ql, kh, vh);

    // 3) tensor-core flash attention -> zh/zl
    cudaFuncSetAttribute(attn_mma, cudaFuncAttributeMaxDynamicSharedMemorySize, ATT_SMEM);
    attn_mma<<<dim3(S_LEN / 64, H_NUM, B_NUM), 128, ATT_SMEM>>>(qh, ql, kh, vh, zh, zl);

    // 4) output projection + residual -> fp32 out
    gemm_f16x2<<<dim3(D_DIM / TILE_N, MROWS / TILE_M), 256, GEMM_SMEM>>>(
        zh, zl, wth + 3 * (size_t)NW, x, out, nullptr, nullptr, nullptr, nullptr);
}

// round 15
// speedup vs baseline: 1.7903x; 1.2301x over previous
#include <cuda_runtime.h>
#include <cuda_fp16.h>
#include <stdint.h>

// Problem dims (fixed)
#define B_NUM 4
#define S_LEN 2048
#define D_DIM 1024
#define H_NUM 16
#define DH 64
#define MROWS (B_NUM * S_LEN)   // 8192

// fp16 operands: GEMM A-side 2-term (hi+lo); Q/K/V hi-only; z hi+lo
__device__ __half g_xh[MROWS * D_DIM];
__device__ __half g_xl[MROWS * D_DIM];
__device__ __half g_qh[MROWS * D_DIM];
__device__ __half g_kh[MROWS * D_DIM];
__device__ __half g_vh[MROWS * D_DIM];
__device__ __half g_zh[MROWS * D_DIM];
__device__ __half g_zl[MROWS * D_DIM];
// transposed weights [n][k], hi only, for Wq,Wk,Wv,Wout (contiguous rows 0..4095)
__device__ __half g_wth[4][D_DIM * D_DIM];

// ---------------------------------------------------------------------------
// Helpers
// ---------------------------------------------------------------------------
__device__ __forceinline__ uint32_t smem_u32(const void* p) {
    uint32_t a;
    asm("{ .reg .u64 t; cvta.to.shared.u64 t, %1; cvt.u32.u64 %0, t; }" : "=r"(a) : "l"(p));
    return a;
}
#define SW128(off) ((off) ^ (((off) >> 3) & 0x70))
__device__ __forceinline__ void cpa16(uint32_t s, const void* g) {
    asm volatile("cp.async.cg.shared.global [%0], [%1], 16;" :: "r"(s), "l"(__cvta_generic_to_global(g)));
}
#define CP_COMMIT() asm volatile("cp.async.commit_group;" ::: "memory")
template <int N> __device__ __forceinline__ void cp_wait() {
    asm volatile("cp.async.wait_group %0;" :: "n"(N) : "memory");
}
__device__ __forceinline__ void ldsm4(uint32_t* r, uint32_t addr) {
    asm volatile("ldmatrix.sync.aligned.m8n8.x4.shared.b16 {%0,%1,%2,%3}, [%4];"
                 : "=r"(r[0]), "=r"(r[1]), "=r"(r[2]), "=r"(r[3]) : "r"(addr));
}
__device__ __forceinline__ void ldsm4t(uint32_t* r, uint32_t addr) {
    asm volatile("ldmatrix.sync.aligned.m8n8.x4.trans.shared.b16 {%0,%1,%2,%3}, [%4];"
                 : "=r"(r[0]), "=r"(r[1]), "=r"(r[2]), "=r"(r[3]) : "r"(addr));
}
__device__ __forceinline__ void mma_f16(float* c, const uint32_t* a, uint32_t b0, uint32_t b1) {
    asm volatile("mma.sync.aligned.m16n8k16.row.col.f32.f16.f16.f32 "
                 "{%0,%1,%2,%3}, {%4,%5,%6,%7}, {%8,%9}, {%0,%1,%2,%3};"
                 : "+f"(c[0]), "+f"(c[1]), "+f"(c[2]), "+f"(c[3])
                 : "r"(a[0]), "r"(a[1]), "r"(a[2]), "r"(a[3]), "r"(b0), "r"(b1));
}
__device__ __forceinline__ uint32_t pack_f16(float x0, float x1) {
    const __half2 h2 = __floats2half2_rn(x0, x1);
    return *(const uint32_t*)&h2;
}
__device__ __forceinline__ void split_pack_f16(float x0, float x1, uint32_t& hp, uint32_t& lp) {
    const __half2 h2 = __floats2half2_rn(x0, x1);
    hp = *(const uint32_t*)&h2;
    const float l0 = x0 - __low2float(h2);
    const float l1 = x1 - __high2float(h2);
    const __half2 l2 = __floats2half2_rn(l0, l1);
    lp = *(const uint32_t*)&l2;
}
__device__ __forceinline__ float ex2_mufu(float y) {
    float r; asm("ex2.approx.f32 %0, %1;" : "=f"(r) : "f"(y)); return r;
}

// ---------------------------------------------------------------------------
// Conversion kernels
// ---------------------------------------------------------------------------
__global__ void k_split(const float* __restrict__ x, __half* __restrict__ h,
                        __half* __restrict__ l, int n) {
    int i = blockIdx.x * blockDim.x + threadIdx.x;
    if (i < n) {
        const float v = x[i];
        const __half hh = __float2half_rn(v);
        h[i] = hh;
        l[i] = __float2half_rn(v - __half2float(hh));
    }
}
__global__ void k_tsplit4(const float* __restrict__ W0, const float* __restrict__ W1,
                          const float* __restrict__ W2, const float* __restrict__ W3,
                          __half* __restrict__ Th) {
    __shared__ float t[32][33];
    const int w = blockIdx.z;
    const float* W = (w == 0) ? W0 : (w == 1) ? W1 : (w == 2) ? W2 : W3;
    const size_t obase = (size_t)w * D_DIM * D_DIM;
    const int n0 = blockIdx.x * 32, k0 = blockIdx.y * 32;
    const int x = threadIdx.x, y = threadIdx.y;  // blockDim (32,8)
#pragma unroll
    for (int r = 0; r < 32; r += 8)
        t[y + r][x] = W[(size_t)(k0 + y + r) * D_DIM + n0 + x];
    __syncthreads();
#pragma unroll
    for (int r = 0; r < 32; r += 8) {
        const float v = t[x][y + r];
        Th[obase + (size_t)(n0 + y + r) * D_DIM + k0 + x] = __float2half_rn(v);
    }
}

// ---------------------------------------------------------------------------
// mma.sync fp16 2-term GEMM: C = (Ah+Al) @ Bh^T (validated R14).
// QKV mode: all three outputs hi-only. Out mode: fp32 + resid.
// ---------------------------------------------------------------------------
#define TILE_M 128
#define TILE_N 128
#define BK 64
#define NITER (D_DIM / BK)          // 16
#define OFF_AH 0
#define OFF_AL 16384
#define OFF_BH 32768
#define STAGE_BYTES 49152           // 48KB
#define GEMM_SMEM (3 * STAGE_BYTES) // 144KB

__device__ __forceinline__ void gemm_loads(
    uint32_t sbase, int tid, int kt, int m0, int n0,
    const __half* Ah, const __half* Al, const __half* Bh)
{
    const int k0 = kt * BK;
#pragma unroll
    for (int c = tid; c < 1024; c += 256) {
        const int row = c >> 3, kc = c & 7;
        const uint32_t sw = SW128((uint32_t)(row * 128 + kc * 16));
        const size_t ga = (size_t)(m0 + row) * D_DIM + k0 + kc * 8;
        const size_t gb = (size_t)(n0 + row) * D_DIM + k0 + kc * 8;
        cpa16(sbase + OFF_AH + sw, Ah + ga);
        cpa16(sbase + OFF_AL + sw, Al + ga);
        cpa16(sbase + OFF_BH + sw, Bh + gb);
    }
    CP_COMMIT();
}

__global__ __launch_bounds__(256, 1)
void gemm_f16x2(const __half* __restrict__ Ah, const __half* __restrict__ Al,
                const __half* __restrict__ Bh,
                const float* __restrict__ resid, float* __restrict__ Cf,
                __half* __restrict__ O0h, __half* __restrict__ O1h,
                __half* __restrict__ O2h)
{
    extern __shared__ __align__(128) char smem[];
    const uint32_t sb = smem_u32(smem);
    const int tid = threadIdx.x, wid = tid >> 5, lane = tid & 31;
    const int warp_m = wid & 3;
    const int warp_n = wid >> 2;
    const int n0 = blockIdx.x * TILE_N;
    const int m0 = blockIdx.y * TILE_M;

    float acc[2][8][4];
#pragma unroll
    for (int mt = 0; mt < 2; mt++)
#pragma unroll
        for (int nt = 0; nt < 8; nt++)
#pragma unroll
            for (int i = 0; i < 4; i++) acc[mt][nt][i] = 0.f;

    gemm_loads(sb, tid, 0, m0, n0, Ah, Al, Bh);
    gemm_loads(sb + STAGE_BYTES, tid, 1, m0, n0, Ah, Al, Bh);
    cp_wait<1>();
    __syncthreads();

    const int arow = warp_m * 32 + (lane & 15);
    const uint32_t acolb = (uint32_t)((lane >> 4) << 4);
    const int brow = warp_n * 64 + ((lane >> 4) << 3) + (lane & 7);
    const uint32_t bcolb = (uint32_t)(((lane >> 3) & 1) << 4);

    for (int it = 0; it < NITER; it++) {
        if (it + 2 < NITER)
            gemm_loads(sb + ((it + 2) % 3) * STAGE_BYTES, tid, it + 2, m0, n0, Ah, Al, Bh);

        const uint32_t s0 = sb + (it % 3) * STAGE_BYTES;
#pragma unroll
        for (int ks = 0; ks < 4; ks++) {
            const uint32_t kb = (uint32_t)(ks * 32);
            uint32_t ah[2][4], al[2][4];
#pragma unroll
            for (int mt = 0; mt < 2; mt++) {
                const uint32_t off = SW128((uint32_t)((arow + mt * 16) * 128) + kb + acolb);
                ldsm4(ah[mt], s0 + OFF_AH + off);
                ldsm4(al[mt], s0 + OFF_AL + off);
            }
            uint32_t bh[4][4];
#pragma unroll
            for (int p = 0; p < 4; p++) {
                const uint32_t off = SW128((uint32_t)((brow + p * 16) * 128) + kb + bcolb);
                ldsm4(bh[p], s0 + OFF_BH + off);
            }
#pragma unroll
            for (int mt = 0; mt < 2; mt++)
#pragma unroll
                for (int p = 0; p < 4; p++)
#pragma unroll
                    for (int hf = 0; hf < 2; hf++) {
                        float* c = acc[mt][p * 2 + hf];
                        mma_f16(c, ah[mt], bh[p][hf * 2], bh[p][hf * 2 + 1]);
                        mma_f16(c, al[mt], bh[p][hf * 2], bh[p][hf * 2 + 1]);
                    }
        }

        if (it + 2 < NITER) cp_wait<1>(); else cp_wait<0>();
        __syncthreads();
    }

    // epilogue: fp32 (+resid) or hi-only fp16 routed by n0>>10
    const int sel = n0 >> 10;
    const int nl = n0 & (D_DIM - 1);
    __half* Oh = (sel == 0) ? O0h : (sel == 1) ? O1h : O2h;
#pragma unroll
    for (int mt = 0; mt < 2; mt++) {
        const int row0 = m0 + warp_m * 32 + mt * 16 + (lane >> 2);
#pragma unroll
        for (int nt = 0; nt < 8; nt++) {
            const int coll = nl + warp_n * 64 + nt * 8 + (lane & 3) * 2;
            const float* c = acc[mt][nt];
            const size_t off = (size_t)row0 * D_DIM + coll;
            if (Cf) {
                float2 v0 = make_float2(c[0], c[1]);
                float2 v1 = make_float2(c[2], c[3]);
                if (resid) {
                    const float2 r0 = *(const float2*)&resid[off];
                    const float2 r1 = *(const float2*)&resid[off + 8 * D_DIM];
                    v0.x += r0.x; v0.y += r0.y; v1.x += r1.x; v1.y += r1.y;
                }
                *(float2*)&Cf[off] = v0;
                *(float2*)&Cf[off + 8 * D_DIM] = v1;
            } else {
                *(uint32_t*)&Oh[off] = pack_f16(c[0], c[1]);
                *(uint32_t*)&Oh[off + 8 * D_DIM] = pack_f16(c[2], c[3]);
            }
        }
    }
}

// ---------------------------------------------------------------------------
// Tensor-core flash attention, plain fp16 internals (Q/K/V/P hi-only),
// fp32 accumulate + fp32 softmax stats; z written as hi+lo split.
// 64 q-rows / 128 threads / 4 warps per CTA, up to 3 CTAs/SM.
// smem: Qh 8K | 3 stages x {Kh 8K, Vh 8K} = 56KB.
// ---------------------------------------------------------------------------
#define ATT_SMEM (8192 + 3 * 16384)    // 57344
#define SLOG2E 0.1803368801111204f     // 0.125 * log2(e)
#define NKV (S_LEN / 64)               // 32

__device__ __forceinline__ void attn_kv_load(
    uint32_t sbase, int tid, size_t kvbase, int k0,
    const __half* kh, const __half* vh)
{
#pragma unroll
    for (int c = tid; c < 512; c += 128) {
        const int row = c >> 3, ch = c & 7;
        const uint32_t sw = SW128((uint32_t)(row * 128 + ch * 16));
        const size_t g = kvbase + (size_t)(k0 + row) * D_DIM + ch * 8;
        cpa16(sbase + sw, kh + g);
        cpa16(sbase + 8192 + sw, vh + g);
    }
    CP_COMMIT();
}

__global__ __launch_bounds__(128, 3)
void attn_mma(const __half* __restrict__ qh,
              const __half* __restrict__ kh, const __half* __restrict__ vh,
              __half* __restrict__ zh, __half* __restrict__ zl)
{
    extern __shared__ __align__(128) char smem[];
    const uint32_t sb = smem_u32(smem);
    const int tid = threadIdx.x, wid = tid >> 5, lane = tid & 31;
    const int q0 = blockIdx.x * 64;
    const int h = blockIdx.y, b = blockIdx.z;
    const size_t qbase = ((size_t)(b * S_LEN + q0)) * D_DIM + h * DH;
    const size_t kvbase = ((size_t)b * S_LEN) * D_DIM + h * DH;
    // 4-way kv stagger to decorrelate co-resident CTAs
    const int phase = (blockIdx.x & 3) * (NKV / 4);

#pragma unroll
    for (int c = tid; c < 256; c += 128) {
        const int row = c >> 2, ch = c & 3;
        // Q: 64 rows x 128B, loaded as 64x8 chunks => 512 chunks/2 per thread... use 512-chunk scheme:
    }
    // Q load (64 rows x 8 chunks = 512)
#pragma unroll
    for (int c = tid; c < 512; c += 128) {
        const int row = c >> 3, ch = c & 7;
        const uint32_t sw = SW128((uint32_t)(row * 128 + ch * 16));
        cpa16(sb + sw, qh + qbase + (size_t)row * D_DIM + ch * 8);
    }
    CP_COMMIT();
    attn_kv_load(sb + 8192, tid, kvbase, (phase & (NKV - 1)) * 64, kh, vh);
    attn_kv_load(sb + 8192 + 16384, tid, kvbase, ((phase + 1) & (NKV - 1)) * 64, kh, vh);
    cp_wait<1>();
    __syncthreads();

    const int arow = wid * 16 + (lane & 15);
    const uint32_t acolb = (uint32_t)((lane >> 4) << 4);
    const int bnrow = ((lane >> 4) << 3) + (lane & 7);
    const uint32_t bncol = (uint32_t)(((lane >> 3) & 1) << 4);
    const int vrow = ((lane >> 3) & 1) * 8 + (lane & 7);
    const uint32_t vcolb = (uint32_t)((lane >> 4) << 4);

    uint32_t qf[4][4];
#pragma unroll
    for (int ks = 0; ks < 4; ks++) {
        const uint32_t off = SW128((uint32_t)(arow * 128) + (uint32_t)(ks * 32) + acolb);
        ldsm4(qf[ks], sb + off);
    }

    float O[8][4];
#pragma unroll
    for (int nt = 0; nt < 8; nt++)
#pragma unroll
        for (int i = 0; i < 4; i++) O[nt][i] = 0.f;
    float m0 = -1.0e30f, m1 = -1.0e30f, l0 = 0.f, l1 = 0.f;

    for (int tt = 0; tt < NKV; tt++) {
        if (tt + 2 < NKV)
            attn_kv_load(sb + 8192 + ((tt + 2) % 3) * 16384, tid, kvbase,
                         ((tt + 2 + phase) & (NKV - 1)) * 64, kh, vh);

        const uint32_t kbB = sb + 8192 + (tt % 3) * 16384;

        // ---- S = Q K^T (1 mma per fragment pair), fp32 accum
        float S[8][4];
#pragma unroll
        for (int nt = 0; nt < 8; nt++)
#pragma unroll
            for (int i = 0; i < 4; i++) S[nt][i] = 0.f;
#pragma unroll
        for (int ks = 0; ks < 4; ks++) {
            uint32_t bh_[4][4];
#pragma unroll
            for (int p = 0; p < 4; p++) {
                const uint32_t off = SW128((uint32_t)((p * 16 + bnrow) * 128) + (uint32_t)(ks * 32) + bncol);
                ldsm4(bh_[p], kbB + off);
            }
#pragma unroll
            for (int p = 0; p < 4; p++)
#pragma unroll
                for (int hf = 0; hf < 2; hf++)
                    mma_f16(S[p * 2 + hf], qf[ks], bh_[p][hf * 2], bh_[p][hf * 2 + 1]);
        }

        // ---- online softmax (all-MUFU; scale folded into exp arg)
        float mx0 = -1.0e30f, mx1 = -1.0e30f;
#pragma unroll
        for (int nt = 0; nt < 8; nt++) {
            mx0 = fmaxf(mx0, fmaxf(S[nt][0], S[nt][1]));
            mx1 = fmaxf(mx1, fmaxf(S[nt][2], S[nt][3]));
        }
        mx0 = fmaxf(mx0, __shfl_xor_sync(0xffffffffu, mx0, 1));
        mx0 = fmaxf(mx0, __shfl_xor_sync(0xffffffffu, mx0, 2));
        mx1 = fmaxf(mx1, __shfl_xor_sync(0xffffffffu, mx1, 1));
        mx1 = fmaxf(mx1, __shfl_xor_sync(0xffffffffu, mx1, 2));
        const float mn0 = fmaxf(m0, mx0), mn1 = fmaxf(m1, mx1);
        const float mb0 = mn0 * SLOG2E, mb1 = mn1 * SLOG2E;
        const float a0 = ex2_mufu(fmaf(m0, SLOG2E, -mb0));
        const float a1 = ex2_mufu(fmaf(m1, SLOG2E, -mb1));
        m0 = mn0; m1 = mn1;

        float s0 = 0.f, s1 = 0.f;
#pragma unroll
        for (int nt = 0; nt < 8; nt++) {
            S[nt][0] = ex2_mufu(fmaf(S[nt][0], SLOG2E, -mb0));
            S[nt][1] = ex2_mufu(fmaf(S[nt][1], SLOG2E, -mb0));
            S[nt][2] = ex2_mufu(fmaf(S[nt][2], SLOG2E, -mb1));
            S[nt][3] = ex2_mufu(fmaf(S[nt][3], SLOG2E, -mb1));
            s0 += S[nt][0] + S[nt][1];
            s1 += S[nt][2] + S[nt][3];
        }
        l0 = l0 * a0 + s0;
        l1 = l1 * a1 + s1;

        if (__ballot_sync(0xffffffffu, (a0 != 1.0f) || (a1 != 1.0f))) {
#pragma unroll
            for (int nt = 0; nt < 8; nt++) {
                O[nt][0] *= a0; O[nt][1] *= a0; O[nt][2] *= a1; O[nt][3] *= a1;
            }
        }

        // ---- P fragments (hi-only) in registers
        uint32_t pf[4][4];
#pragma unroll
        for (int ks = 0; ks < 4; ks++) {
            pf[ks][0] = pack_f16(S[2 * ks][0], S[2 * ks][1]);
            pf[ks][1] = pack_f16(S[2 * ks][2], S[2 * ks][3]);
            pf[ks][2] = pack_f16(S[2 * ks + 1][0], S[2 * ks + 1][1]);
            pf[ks][3] = pack_f16(S[2 * ks + 1][2], S[2 * ks + 1][3]);
        }

        // ---- O += P Vh (1 mma per fragment pair)
#pragma unroll
        for (int ks = 0; ks < 4; ks++) {
            uint32_t vh_[4][4];
#pragma unroll
            for (int p = 0; p < 4; p++) {
                const uint32_t off = SW128((uint32_t)((ks * 16 + vrow) * 128) + (uint32_t)(p * 32) + vcolb);
                ldsm4t(vh_[p], kbB + 8192 + off);
            }
#pragma unroll
            for (int p = 0; p < 4; p++)
#pragma unroll
                for (int hf = 0; hf < 2; hf++)
                    mma_f16(O[p * 2 + hf], pf[ks], vh_[p][hf * 2], vh_[p][hf * 2 + 1]);
        }

        if (tt + 2 < NKV) cp_wait<1>(); else cp_wait<0>();
        __syncthreads();
    }

    l0 += __shfl_xor_sync(0xffffffffu, l0, 1);
    l0 += __shfl_xor_sync(0xffffffffu, l0, 2);
    l1 += __shfl_xor_sync(0xffffffffu, l1, 1);
    l1 += __shfl_xor_sync(0xffffffffu, l1, 2);
    const float inv0 = 1.0f / l0, inv1 = 1.0f / l1;

    // z written as hi+lo split (free accuracy from fp32 O)
    const int rowg = b * S_LEN + q0 + wid * 16 + (lane >> 2);
#pragma unroll
    for (int nt = 0; nt < 8; nt++) {
        const int col = h * DH + nt * 8 + (lane & 3) * 2;
        uint32_t hp, lp;
        split_pack_f16(O[nt][0] * inv0, O[nt][1] * inv0, hp, lp);
        size_t off = (size_t)rowg * D_DIM + col;
        *(uint32_t*)&zh[off] = hp; *(uint32_t*)&zl[off] = lp;
        split_pack_f16(O[nt][2] * inv1, O[nt][3] * inv1, hp, lp);
        off += (size_t)8 * D_DIM;
        *(uint32_t*)&zh[off] = hp; *(uint32_t*)&zl[off] = lp;
    }
}

// ---------------------------------------------------------------------------
// Inputs (metadata order): x, mask(bool, unused), Wq, Wk, Wv, Wout
// ---------------------------------------------------------------------------
extern "C" void kernel_launch(void* const* d_in, const int* in_sizes, int n_in,
                              void* d_out, int out_size)
{
    (void)in_sizes; (void)n_in; (void)out_size;
    const float* x    = (const float*)d_in[0];
    const float* Wq   = (const float*)d_in[2];
    const float* Wk   = (const float*)d_in[3];
    const float* Wv   = (const float*)d_in[4];
    const float* Wout = (const float*)d_in[5];
    float* out = (float*)d_out;

    __half *xh, *xl, *qh, *kh, *vh, *zh, *zl, *wth;
    cudaGetSymbolAddress((void**)&xh, g_xh);
    cudaGetSymbolAddress((void**)&xl, g_xl);
    cudaGetSymbolAddress((void**)&qh, g_qh);
    cudaGetSymbolAddress((void**)&kh, g_kh);
    cudaGetSymbolAddress((void**)&vh, g_vh);
    cudaGetSymbolAddress((void**)&zh, g_zh);
    cudaGetSymbolAddress((void**)&zl, g_zl);
    cudaGetSymbolAddress((void**)&wth, g_wth);

    const int NW = D_DIM * D_DIM;

    // 1) split x (hi+lo); transpose weights hi-only
    k_split<<<(MROWS * D_DIM + 255) / 256, 256>>>(x, xh, xl, MROWS * D_DIM);
    k_tsplit4<<<dim3(D_DIM / 32, D_DIM / 32, 4), dim3(32, 8)>>>(Wq, Wk, Wv, Wout, wth);

    // 2) merged QKV projection (N=3072): Q/K/V all hi-only
    cudaFuncSetAttribute(gemm_f16x2, cudaFuncAttributeMaxDynamicSharedMemorySize, GEMM_SMEM);
    gemm_f16x2<<<dim3(3 * D_DIM / TILE_N, MROWS / TILE_M), 256, GEMM_SMEM>>>(
        xh, xl, wth, nullptr, nullptr, qh, kh, vh);

    // 3) tensor-core flash attention (plain fp16 internals) -> zh/zl
    cudaFuncSetAttribute(attn_mma, cudaFuncAttributeMaxDynamicSharedMemorySize, ATT_SMEM);
    attn_mma<<<dim3(S_LEN / 64, H_NUM, B_NUM), 128, ATT_SMEM>>>(qh, kh, vh, zh, zl);

    // 4) output projection + residual -> fp32 out (A-side keeps 2-term)
    gemm_f16x2<<<dim3(D_DIM / TILE_N, MROWS / TILE_M), 256, GEMM_SMEM>>>(
        zh, zl, wth + 3 * (size_t)NW, x, out, nullptr, nullptr, nullptr);
}

// round 16
// speedup vs baseline: 2.3055x; 1.2878x over previous
#include <cuda_runtime.h>
#include <cuda_fp16.h>
#include <stdint.h>

// Problem dims (fixed)
#define B_NUM 4
#define S_LEN 2048
#define D_DIM 1024
#define H_NUM 16
#define DH 64
#define MROWS (B_NUM * S_LEN)   // 8192

// fp16 operands, all hi-only
__device__ __half g_xh[MROWS * D_DIM];
__device__ __half g_qh[MROWS * D_DIM];
__device__ __half g_kh[MROWS * D_DIM];
__device__ __half g_vh[MROWS * D_DIM];
__device__ __half g_zh[MROWS * D_DIM];
// transposed weights [n][k], hi only, for Wq,Wk,Wv,Wout (contiguous rows 0..4095)
__device__ __half g_wth[4][D_DIM * D_DIM];

// ---------------------------------------------------------------------------
// Helpers
// ---------------------------------------------------------------------------
__device__ __forceinline__ uint32_t smem_u32(const void* p) {
    uint32_t a;
    asm("{ .reg .u64 t; cvta.to.shared.u64 t, %1; cvt.u32.u64 %0, t; }" : "=r"(a) : "l"(p));
    return a;
}
#define SW128(off) ((off) ^ (((off) >> 3) & 0x70))
__device__ __forceinline__ void cpa16(uint32_t s, const void* g) {
    asm volatile("cp.async.cg.shared.global [%0], [%1], 16;" :: "r"(s), "l"(__cvta_generic_to_global(g)));
}
#define CP_COMMIT() asm volatile("cp.async.commit_group;" ::: "memory")
template <int N> __device__ __forceinline__ void cp_wait() {
    asm volatile("cp.async.wait_group %0;" :: "n"(N) : "memory");
}
__device__ __forceinline__ void ldsm4(uint32_t* r, uint32_t addr) {
    asm volatile("ldmatrix.sync.aligned.m8n8.x4.shared.b16 {%0,%1,%2,%3}, [%4];"
                 : "=r"(r[0]), "=r"(r[1]), "=r"(r[2]), "=r"(r[3]) : "r"(addr));
}
__device__ __forceinline__ void ldsm4t(uint32_t* r, uint32_t addr) {
    asm volatile("ldmatrix.sync.aligned.m8n8.x4.trans.shared.b16 {%0,%1,%2,%3}, [%4];"
                 : "=r"(r[0]), "=r"(r[1]), "=r"(r[2]), "=r"(r[3]) : "r"(addr));
}
__device__ __forceinline__ void mma_f16(float* c, const uint32_t* a, uint32_t b0, uint32_t b1) {
    asm volatile("mma.sync.aligned.m16n8k16.row.col.f32.f16.f16.f32 "
                 "{%0,%1,%2,%3}, {%4,%5,%6,%7}, {%8,%9}, {%0,%1,%2,%3};"
                 : "+f"(c[0]), "+f"(c[1]), "+f"(c[2]), "+f"(c[3])
                 : "r"(a[0]), "r"(a[1]), "r"(a[2]), "r"(a[3]), "r"(b0), "r"(b1));
}
__device__ __forceinline__ uint32_t pack_f16(float x0, float x1) {
    const __half2 h2 = __floats2half2_rn(x0, x1);
    return *(const uint32_t*)&h2;
}
__device__ __forceinline__ float ex2_mufu(float y) {
    float r; asm("ex2.approx.f32 %0, %1;" : "=f"(r) : "f"(y)); return r;
}

// ---------------------------------------------------------------------------
// Conversion kernels
// ---------------------------------------------------------------------------
__global__ void k_cast(const float* __restrict__ x, __half* __restrict__ h, int n) {
    int i = blockIdx.x * blockDim.x + threadIdx.x;
    if (i < n) h[i] = __float2half_rn(x[i]);
}
__global__ void k_tsplit4(const float* __restrict__ W0, const float* __restrict__ W1,
                          const float* __restrict__ W2, const float* __restrict__ W3,
                          __half* __restrict__ Th) {
    __shared__ float t[32][33];
    const int w = blockIdx.z;
    const float* W = (w == 0) ? W0 : (w == 1) ? W1 : (w == 2) ? W2 : W3;
    const size_t obase = (size_t)w * D_DIM * D_DIM;
    const int n0 = blockIdx.x * 32, k0 = blockIdx.y * 32;
    const int x = threadIdx.x, y = threadIdx.y;  // blockDim (32,8)
#pragma unroll
    for (int r = 0; r < 32; r += 8)
        t[y + r][x] = W[(size_t)(k0 + y + r) * D_DIM + n0 + x];
    __syncthreads();
#pragma unroll
    for (int r = 0; r < 32; r += 8) {
        const float v = t[x][y + r];
        Th[obase + (size_t)(n0 + y + r) * D_DIM + k0 + x] = __float2half_rn(v);
    }
}

// ---------------------------------------------------------------------------
// mma.sync plain-fp16 GEMM: C = Ah @ Bh^T, fp32 accum, 3-stage pipeline,
// 256 threads / 8 warps / 32x64 warp tiles (validated config).
// ---------------------------------------------------------------------------
#define TILE_M 128
#define TILE_N 128
#define BK 64
#define NITER (D_DIM / BK)          // 16
#define OFF_AH 0
#define OFF_BH 16384
#define STAGE_BYTES 32768           // 32KB
#define GEMM_SMEM (3 * STAGE_BYTES) // 96KB

__device__ __forceinline__ void gemm_loads(
    uint32_t sbase, int tid, int kt, int m0, int n0,
    const __half* Ah, const __half* Bh)
{
    const int k0 = kt * BK;
#pragma unroll
    for (int c = tid; c < 1024; c += 256) {
        const int row = c >> 3, kc = c & 7;
        const uint32_t sw = SW128((uint32_t)(row * 128 + kc * 16));
        cpa16(sbase + OFF_AH + sw, Ah + (size_t)(m0 + row) * D_DIM + k0 + kc * 8);
        cpa16(sbase + OFF_BH + sw, Bh + (size_t)(n0 + row) * D_DIM + k0 + kc * 8);
    }
    CP_COMMIT();
}

__global__ __launch_bounds__(256, 1)
void gemm_f16(const __half* __restrict__ Ah, const __half* __restrict__ Bh,
              const float* __restrict__ resid, float* __restrict__ Cf,
              __half* __restrict__ O0h, __half* __restrict__ O1h,
              __half* __restrict__ O2h)
{
    extern __shared__ __align__(128) char smem[];
    const uint32_t sb = smem_u32(smem);
    const int tid = threadIdx.x, wid = tid >> 5, lane = tid & 31;
    const int warp_m = wid & 3;
    const int warp_n = wid >> 2;
    const int n0 = blockIdx.x * TILE_N;
    const int m0 = blockIdx.y * TILE_M;

    float acc[2][8][4];
#pragma unroll
    for (int mt = 0; mt < 2; mt++)
#pragma unroll
        for (int nt = 0; nt < 8; nt++)
#pragma unroll
            for (int i = 0; i < 4; i++) acc[mt][nt][i] = 0.f;

    gemm_loads(sb, tid, 0, m0, n0, Ah, Bh);
    gemm_loads(sb + STAGE_BYTES, tid, 1, m0, n0, Ah, Bh);
    cp_wait<1>();
    __syncthreads();

    const int arow = warp_m * 32 + (lane & 15);
    const uint32_t acolb = (uint32_t)((lane >> 4) << 4);
    const int brow = warp_n * 64 + ((lane >> 4) << 3) + (lane & 7);
    const uint32_t bcolb = (uint32_t)(((lane >> 3) & 1) << 4);

    for (int it = 0; it < NITER; it++) {
        if (it + 2 < NITER)
            gemm_loads(sb + ((it + 2) % 3) * STAGE_BYTES, tid, it + 2, m0, n0, Ah, Bh);

        const uint32_t s0 = sb + (it % 3) * STAGE_BYTES;
#pragma unroll
        for (int ks = 0; ks < 4; ks++) {
            const uint32_t kb = (uint32_t)(ks * 32);
            uint32_t ah[2][4];
#pragma unroll
            for (int mt = 0; mt < 2; mt++) {
                const uint32_t off = SW128((uint32_t)((arow + mt * 16) * 128) + kb + acolb);
                ldsm4(ah[mt], s0 + OFF_AH + off);
            }
            uint32_t bh[4][4];
#pragma unroll
            for (int p = 0; p < 4; p++) {
                const uint32_t off = SW128((uint32_t)((brow + p * 16) * 128) + kb + bcolb);
                ldsm4(bh[p], s0 + OFF_BH + off);
            }
#pragma unroll
            for (int mt = 0; mt < 2; mt++)
#pragma unroll
                for (int p = 0; p < 4; p++)
#pragma unroll
                    for (int hf = 0; hf < 2; hf++)
                        mma_f16(acc[mt][p * 2 + hf], ah[mt], bh[p][hf * 2], bh[p][hf * 2 + 1]);
        }

        if (it + 2 < NITER) cp_wait<1>(); else cp_wait<0>();
        __syncthreads();
    }

    // epilogue: fp32 (+resid) or hi-only fp16 routed by n0>>10
    const int sel = n0 >> 10;
    const int nl = n0 & (D_DIM - 1);
    __half* Oh = (sel == 0) ? O0h : (sel == 1) ? O1h : O2h;
#pragma unroll
    for (int mt = 0; mt < 2; mt++) {
        const int row0 = m0 + warp_m * 32 + mt * 16 + (lane >> 2);
#pragma unroll
        for (int nt = 0; nt < 8; nt++) {
            const int coll = nl + warp_n * 64 + nt * 8 + (lane & 3) * 2;
            const float* c = acc[mt][nt];
            const size_t off = (size_t)row0 * D_DIM + coll;
            if (Cf) {
                float2 v0 = make_float2(c[0], c[1]);
                float2 v1 = make_float2(c[2], c[3]);
                if (resid) {
                    const float2 r0 = *(const float2*)&resid[off];
                    const float2 r1 = *(const float2*)&resid[off + 8 * D_DIM];
                    v0.x += r0.x; v0.y += r0.y; v1.x += r1.x; v1.y += r1.y;
                }
                *(float2*)&Cf[off] = v0;
                *(float2*)&Cf[off + 8 * D_DIM] = v1;
            } else {
                *(uint32_t*)&Oh[off] = pack_f16(c[0], c[1]);
                *(uint32_t*)&Oh[off + 8 * D_DIM] = pack_f16(c[2], c[3]);
            }
        }
    }
}

// ---------------------------------------------------------------------------
// Tensor-core flash attention, plain fp16 internals (validated R15),
// z written hi-only. 64 q-rows / 128 threads / 4 warps, 3 CTAs/SM.
// smem: Qh 8K | 3 stages x {Kh 8K, Vh 8K} = 56KB.
// ---------------------------------------------------------------------------
#define ATT_SMEM (8192 + 3 * 16384)    // 57344
#define SLOG2E 0.1803368801111204f     // 0.125 * log2(e)
#define NKV (S_LEN / 64)               // 32

__device__ __forceinline__ void attn_kv_load(
    uint32_t sbase, int tid, size_t kvbase, int k0,
    const __half* kh, const __half* vh)
{
#pragma unroll
    for (int c = tid; c < 512; c += 128) {
        const int row = c >> 3, ch = c & 7;
        const uint32_t sw = SW128((uint32_t)(row * 128 + ch * 16));
        const size_t g = kvbase + (size_t)(k0 + row) * D_DIM + ch * 8;
        cpa16(sbase + sw, kh + g);
        cpa16(sbase + 8192 + sw, vh + g);
    }
    CP_COMMIT();
}

__global__ __launch_bounds__(128, 3)
void attn_mma(const __half* __restrict__ qh,
              const __half* __restrict__ kh, const __half* __restrict__ vh,
              __half* __restrict__ zh)
{
    extern __shared__ __align__(128) char smem[];
    const uint32_t sb = smem_u32(smem);
    const int tid = threadIdx.x, wid = tid >> 5, lane = tid & 31;
    const int q0 = blockIdx.x * 64;
    const int h = blockIdx.y, b = blockIdx.z;
    const size_t qbase = ((size_t)(b * S_LEN + q0)) * D_DIM + h * DH;
    const size_t kvbase = ((size_t)b * S_LEN) * D_DIM + h * DH;
    // 4-way kv stagger to decorrelate co-resident CTAs
    const int phase = (blockIdx.x & 3) * (NKV / 4);

    // Q load (64 rows x 8 chunks = 512)
#pragma unroll
    for (int c = tid; c < 512; c += 128) {
        const int row = c >> 3, ch = c & 7;
        const uint32_t sw = SW128((uint32_t)(row * 128 + ch * 16));
        cpa16(sb + sw, qh + qbase + (size_t)row * D_DIM + ch * 8);
    }
    CP_COMMIT();
    attn_kv_load(sb + 8192, tid, kvbase, (phase & (NKV - 1)) * 64, kh, vh);
    attn_kv_load(sb + 8192 + 16384, tid, kvbase, ((phase + 1) & (NKV - 1)) * 64, kh, vh);
    cp_wait<1>();
    __syncthreads();

    const int arow = wid * 16 + (lane & 15);
    const uint32_t acolb = (uint32_t)((lane >> 4) << 4);
    const int bnrow = ((lane >> 4) << 3) + (lane & 7);
    const uint32_t bncol = (uint32_t)(((lane >> 3) & 1) << 4);
    const int vrow = ((lane >> 3) & 1) * 8 + (lane & 7);
    const uint32_t vcolb = (uint32_t)((lane >> 4) << 4);

    uint32_t qf[4][4];
#pragma unroll
    for (int ks = 0; ks < 4; ks++) {
        const uint32_t off = SW128((uint32_t)(arow * 128) + (uint32_t)(ks * 32) + acolb);
        ldsm4(qf[ks], sb + off);
    }

    float O[8][4];
#pragma unroll
    for (int nt = 0; nt < 8; nt++)
#pragma unroll
        for (int i = 0; i < 4; i++) O[nt][i] = 0.f;
    float m0 = -1.0e30f, m1 = -1.0e30f, l0 = 0.f, l1 = 0.f;

    for (int tt = 0; tt < NKV; tt++) {
        if (tt + 2 < NKV)
            attn_kv_load(sb + 8192 + ((tt + 2) % 3) * 16384, tid, kvbase,
                         ((tt + 2 + phase) & (NKV - 1)) * 64, kh, vh);

        const uint32_t kbB = sb + 8192 + (tt % 3) * 16384;

        // ---- S = Q K^T, fp32 accum
        float S[8][4];
#pragma unroll
        for (int nt = 0; nt < 8; nt++)
#pragma unroll
            for (int i = 0; i < 4; i++) S[nt][i] = 0.f;
#pragma unroll
        for (int ks = 0; ks < 4; ks++) {
            uint32_t bh_[4][4];
#pragma unroll
            for (int p = 0; p < 4; p++) {
                const uint32_t off = SW128((uint32_t)((p * 16 + bnrow) * 128) + (uint32_t)(ks * 32) + bncol);
                ldsm4(bh_[p], kbB + off);
            }
#pragma unroll
            for (int p = 0; p < 4; p++)
#pragma unroll
                for (int hf = 0; hf < 2; hf++)
                    mma_f16(S[p * 2 + hf], qf[ks], bh_[p][hf * 2], bh_[p][hf * 2 + 1]);
        }

        // ---- online softmax (all-MUFU; scale folded into exp arg)
        float mx0 = -1.0e30f, mx1 = -1.0e30f;
#pragma unroll
        for (int nt = 0; nt < 8; nt++) {
            mx0 = fmaxf(mx0, fmaxf(S[nt][0], S[nt][1]));
            mx1 = fmaxf(mx1, fmaxf(S[nt][2], S[nt][3]));
        }
        mx0 = fmaxf(mx0, __shfl_xor_sync(0xffffffffu, mx0, 1));
        mx0 = fmaxf(mx0, __shfl_xor_sync(0xffffffffu, mx0, 2));
        mx1 = fmaxf(mx1, __shfl_xor_sync(0xffffffffu, mx1, 1));
        mx1 = fmaxf(mx1, __shfl_xor_sync(0xffffffffu, mx1, 2));
        const float mn0 = fmaxf(m0, mx0), mn1 = fmaxf(m1, mx1);
        const float mb0 = mn0 * SLOG2E, mb1 = mn1 * SLOG2E;
        const float a0 = ex2_mufu(fmaf(m0, SLOG2E, -mb0));
        const float a1 = ex2_mufu(fmaf(m1, SLOG2E, -mb1));
        m0 = mn0; m1 = mn1;

        float s0 = 0.f, s1 = 0.f;
#pragma unroll
        for (int nt = 0; nt < 8; nt++) {
            S[nt][0] = ex2_mufu(fmaf(S[nt][0], SLOG2E, -mb0));
            S[nt][1] = ex2_mufu(fmaf(S[nt][1], SLOG2E, -mb0));
            S[nt][2] = ex2_mufu(fmaf(S[nt][2], SLOG2E, -mb1));
            S[nt][3] = ex2_mufu(fmaf(S[nt][3], SLOG2E, -mb1));
            s0 += S[nt][0] + S[nt][1];
            s1 += S[nt][2] + S[nt][3];
        }
        l0 = l0 * a0 + s0;
        l1 = l1 * a1 + s1;

        if (__ballot_sync(0xffffffffu, (a0 != 1.0f) || (a1 != 1.0f))) {
#pragma unroll
            for (int nt = 0; nt < 8; nt++) {
                O[nt][0] *= a0; O[nt][1] *= a0; O[nt][2] *= a1; O[nt][3] *= a1;
            }
        }

        // ---- P fragments (hi-only) in registers
        uint32_t pf[4][4];
#pragma unroll
        for (int ks = 0; ks < 4; ks++) {
            pf[ks][0] = pack_f16(S[2 * ks][0], S[2 * ks][1]);
            pf[ks][1] = pack_f16(S[2 * ks][2], S[2 * ks][3]);
            pf[ks][2] = pack_f16(S[2 * ks + 1][0], S[2 * ks + 1][1]);
            pf[ks][3] = pack_f16(S[2 * ks + 1][2], S[2 * ks + 1][3]);
        }

        // ---- O += P Vh
#pragma unroll
        for (int ks = 0; ks < 4; ks++) {
            uint32_t vh_[4][4];
#pragma unroll
            for (int p = 0; p < 4; p++) {
                const uint32_t off = SW128((uint32_t)((ks * 16 + vrow) * 128) + (uint32_t)(p * 32) + vcolb);
                ldsm4t(vh_[p], kbB + 8192 + off);
            }
#pragma unroll
            for (int p = 0; p < 4; p++)
#pragma unroll
                for (int hf = 0; hf < 2; hf++)
                    mma_f16(O[p * 2 + hf], pf[ks], vh_[p][hf * 2], vh_[p][hf * 2 + 1]);
        }

        if (tt + 2 < NKV) cp_wait<1>(); else cp_wait<0>();
        __syncthreads();
    }

    l0 += __shfl_xor_sync(0xffffffffu, l0, 1);
    l0 += __shfl_xor_sync(0xffffffffu, l0, 2);
    l1 += __shfl_xor_sync(0xffffffffu, l1, 1);
    l1 += __shfl_xor_sync(0xffffffffu, l1, 2);
    const float inv0 = 1.0f / l0, inv1 = 1.0f / l1;

    const int rowg = b * S_LEN + q0 + wid * 16 + (lane >> 2);
#pragma unroll
    for (int nt = 0; nt < 8; nt++) {
        const int col = h * DH + nt * 8 + (lane & 3) * 2;
        size_t off = (size_t)rowg * D_DIM + col;
        *(uint32_t*)&zh[off] = pack_f16(O[nt][0] * inv0, O[nt][1] * inv0);
        *(uint32_t*)&zh[off + 8 * D_DIM] = pack_f16(O[nt][2] * inv1, O[nt][3] * inv1);
    }
}

// ---------------------------------------------------------------------------
// Inputs (metadata order): x, mask(bool, unused), Wq, Wk, Wv, Wout
// ---------------------------------------------------------------------------
extern "C" void kernel_launch(void* const* d_in, const int* in_sizes, int n_in,
                              void* d_out, int out_size)
{
    (void)in_sizes; (void)n_in; (void)out_size;
    const float* x    = (const float*)d_in[0];
    const float* Wq   = (const float*)d_in[2];
    const float* Wk   = (const float*)d_in[3];
    const float* Wv   = (const float*)d_in[4];
    const float* Wout = (const float*)d_in[5];
    float* out = (float*)d_out;

    __half *xh, *qh, *kh, *vh, *zh, *wth;
    cudaGetSymbolAddress((void**)&xh, g_xh);
    cudaGetSymbolAddress((void**)&qh, g_qh);
    cudaGetSymbolAddress((void**)&kh, g_kh);
    cudaGetSymbolAddress((void**)&vh, g_vh);
    cudaGetSymbolAddress((void**)&zh, g_zh);
    cudaGetSymbolAddress((void**)&wth, g_wth);

    const int NW = D_DIM * D_DIM;

    // 1) cast x to fp16; transpose weights hi-only
    k_cast<<<(MROWS * D_DIM + 255) / 256, 256>>>(x, xh, MROWS * D_DIM);
    k_tsplit4<<<dim3(D_DIM / 32, D_DIM / 32, 4), dim3(32, 8)>>>(Wq, Wk, Wv, Wout, wth);

    // 2) merged QKV projection (N=3072), plain fp16
    cudaFuncSetAttribute(gemm_f16, cudaFuncAttributeMaxDynamicSharedMemorySize, GEMM_SMEM);
    gemm_f16<<<dim3(3 * D_DIM / TILE_N, MROWS / TILE_M), 256, GEMM_SMEM>>>(
        xh, wth, nullptr, nullptr, qh, kh, vh);

    // 3) tensor-core flash attention -> zh
    cudaFuncSetAttribute(attn_mma, cudaFuncAttributeMaxDynamicSharedMemorySize, ATT_SMEM);
    attn_mma<<<dim3(S_LEN / 64, H_NUM, B_NUM), 128, ATT_SMEM>>>(qh, kh, vh, zh);

    // 4) output projection + residual -> fp32 out
    gemm_f16<<<dim3(D_DIM / TILE_N, MROWS / TILE_M), 256, GEMM_SMEM>>>(
        zh, wth + 3 * (size_t)NW, x, out, nullptr, nullptr, nullptr);
}

// round 17
// speedup vs baseline: 2.3695x; 1.0277x over previous
#include <cuda_runtime.h>
#include <cuda_fp16.h>
#include <stdint.h>

// Problem dims (fixed)
#define B_NUM 4
#define S_LEN 2048
#define D_DIM 1024
#define H_NUM 16
#define DH 64
#define MROWS (B_NUM * S_LEN)   // 8192

// fp16 operands, all hi-only
__device__ __half g_xh[MROWS * D_DIM];
__device__ __half g_qh[MROWS * D_DIM];
__device__ __half g_kh[MROWS * D_DIM];
__device__ __half g_vh[MROWS * D_DIM];
__device__ __half g_zh[MROWS * D_DIM];
// transposed weights [n][k], hi only, for Wq,Wk,Wv,Wout (contiguous rows 0..4095)
__device__ __half g_wth[4][D_DIM * D_DIM];

// ---------------------------------------------------------------------------
// Helpers
// ---------------------------------------------------------------------------
__device__ __forceinline__ uint32_t smem_u32(const void* p) {
    uint32_t a;
    asm("{ .reg .u64 t; cvta.to.shared.u64 t, %1; cvt.u32.u64 %0, t; }" : "=r"(a) : "l"(p));
    return a;
}
#define SW128(off) ((off) ^ (((off) >> 3) & 0x70))
__device__ __forceinline__ void cpa16(uint32_t s, const void* g) {
    asm volatile("cp.async.cg.shared.global [%0], [%1], 16;" :: "r"(s), "l"(__cvta_generic_to_global(g)));
}
#define CP_COMMIT() asm volatile("cp.async.commit_group;" ::: "memory")
template <int N> __device__ __forceinline__ void cp_wait() {
    asm volatile("cp.async.wait_group %0;" :: "n"(N) : "memory");
}
__device__ __forceinline__ void ldsm4(uint32_t* r, uint32_t addr) {
    asm volatile("ldmatrix.sync.aligned.m8n8.x4.shared.b16 {%0,%1,%2,%3}, [%4];"
                 : "=r"(r[0]), "=r"(r[1]), "=r"(r[2]), "=r"(r[3]) : "r"(addr));
}
__device__ __forceinline__ void ldsm4t(uint32_t* r, uint32_t addr) {
    asm volatile("ldmatrix.sync.aligned.m8n8.x4.trans.shared.b16 {%0,%1,%2,%3}, [%4];"
                 : "=r"(r[0]), "=r"(r[1]), "=r"(r[2]), "=r"(r[3]) : "r"(addr));
}
__device__ __forceinline__ void mma_f16(float* c, const uint32_t* a, uint32_t b0, uint32_t b1) {
    asm volatile("mma.sync.aligned.m16n8k16.row.col.f32.f16.f16.f32 "
                 "{%0,%1,%2,%3}, {%4,%5,%6,%7}, {%8,%9}, {%0,%1,%2,%3};"
                 : "+f"(c[0]), "+f"(c[1]), "+f"(c[2]), "+f"(c[3])
                 : "r"(a[0]), "r"(a[1]), "r"(a[2]), "r"(a[3]), "r"(b0), "r"(b1));
}
__device__ __forceinline__ uint32_t pack_f16(float x0, float x1) {
    const __half2 h2 = __floats2half2_rn(x0, x1);
    return *(const uint32_t*)&h2;
}
__device__ __forceinline__ float ex2_mufu(float y) {
    float r; asm("ex2.approx.f32 %0, %1;" : "=f"(r) : "f"(y)); return r;
}
// FMA-pipe exp2 (validated in R8): |err| ~ 2.4e-6, y <= 0
__device__ __forceinline__ float ex2_poly(float y) {
    y = fmaxf(y, -126.0f);
    const float zb = y + 12582912.0f;            // RN to integer (magic 1.5*2^23)
    const int nb = __float_as_int(zb);
    const float f = y - (zb - 12582912.0f);      // f in [-0.5, 0.5]
    float p = fmaf(f, 0.0013333558f, 0.0096181291f);
    p = fmaf(p, f, 0.0555041087f);
    p = fmaf(p, f, 0.2402265070f);
    p = fmaf(p, f, 0.6931471806f);
    p = fmaf(p, f, 1.0f);
    return p * __int_as_float((nb + (127 - 0x4B400000)) << 23);
}

// ---------------------------------------------------------------------------
// Conversion kernels
// ---------------------------------------------------------------------------
__global__ void k_cast(const float* __restrict__ x, __half* __restrict__ h, int n) {
    int i = blockIdx.x * blockDim.x + threadIdx.x;
    if (i < n) h[i] = __float2half_rn(x[i]);
}
__global__ void k_tsplit4(const float* __restrict__ W0, const float* __restrict__ W1,
                          const float* __restrict__ W2, const float* __restrict__ W3,
                          __half* __restrict__ Th) {
    __shared__ float t[32][33];
    const int w = blockIdx.z;
    const float* W = (w == 0) ? W0 : (w == 1) ? W1 : (w == 2) ? W2 : W3;
    const size_t obase = (size_t)w * D_DIM * D_DIM;
    const int n0 = blockIdx.x * 32, k0 = blockIdx.y * 32;
    const int x = threadIdx.x, y = threadIdx.y;  // blockDim (32,8)
#pragma unroll
    for (int r = 0; r < 32; r += 8)
        t[y + r][x] = W[(size_t)(k0 + y + r) * D_DIM + n0 + x];
    __syncthreads();
#pragma unroll
    for (int r = 0; r < 32; r += 8) {
        const float v = t[x][y + r];
        Th[obase + (size_t)(n0 + y + r) * D_DIM + k0 + x] = __float2half_rn(v);
    }
}

// ---------------------------------------------------------------------------
// mma.sync plain-fp16 GEMM: C = Ah @ Bh^T, fp32 accum, 3-stage pipeline,
// 256 threads / 8 warps / 32x64 warp tiles. R17: 2 CTAs/SM (96KB smem each).
// ---------------------------------------------------------------------------
#define TILE_M 128
#define TILE_N 128
#define BK 64
#define NITER (D_DIM / BK)          // 16
#define OFF_AH 0
#define OFF_BH 16384
#define STAGE_BYTES 32768           // 32KB
#define GEMM_SMEM (3 * STAGE_BYTES) // 96KB

__device__ __forceinline__ void gemm_loads(
    uint32_t sbase, int tid, int kt, int m0, int n0,
    const __half* Ah, const __half* Bh)
{
    const int k0 = kt * BK;
#pragma unroll
    for (int c = tid; c < 1024; c += 256) {
        const int row = c >> 3, kc = c & 7;
        const uint32_t sw = SW128((uint32_t)(row * 128 + kc * 16));
        cpa16(sbase + OFF_AH + sw, Ah + (size_t)(m0 + row) * D_DIM + k0 + kc * 8);
        cpa16(sbase + OFF_BH + sw, Bh + (size_t)(n0 + row) * D_DIM + k0 + kc * 8);
    }
    CP_COMMIT();
}

__global__ __launch_bounds__(256, 2)
void gemm_f16(const __half* __restrict__ Ah, const __half* __restrict__ Bh,
              const float* __restrict__ resid, float* __restrict__ Cf,
              __half* __restrict__ O0h, __half* __restrict__ O1h,
              __half* __restrict__ O2h)
{
    extern __shared__ __align__(128) char smem[];
    const uint32_t sb = smem_u32(smem);
    const int tid = threadIdx.x, wid = tid >> 5, lane = tid & 31;
    const int warp_m = wid & 3;
    const int warp_n = wid >> 2;
    const int n0 = blockIdx.x * TILE_N;
    const int m0 = blockIdx.y * TILE_M;

    float acc[2][8][4];
#pragma unroll
    for (int mt = 0; mt < 2; mt++)
#pragma unroll
        for (int nt = 0; nt < 8; nt++)
#pragma unroll
            for (int i = 0; i < 4; i++) acc[mt][nt][i] = 0.f;

    gemm_loads(sb, tid, 0, m0, n0, Ah, Bh);
    gemm_loads(sb + STAGE_BYTES, tid, 1, m0, n0, Ah, Bh);
    cp_wait<1>();
    __syncthreads();

    const int arow = warp_m * 32 + (lane & 15);
    const uint32_t acolb = (uint32_t)((lane >> 4) << 4);
    const int brow = warp_n * 64 + ((lane >> 4) << 3) + (lane & 7);
    const uint32_t bcolb = (uint32_t)(((lane >> 3) & 1) << 4);

    for (int it = 0; it < NITER; it++) {
        if (it + 2 < NITER)
            gemm_loads(sb + ((it + 2) % 3) * STAGE_BYTES, tid, it + 2, m0, n0, Ah, Bh);

        const uint32_t s0 = sb + (it % 3) * STAGE_BYTES;
#pragma unroll
        for (int ks = 0; ks < 4; ks++) {
            const uint32_t kb = (uint32_t)(ks * 32);
            uint32_t ah[2][4];
#pragma unroll
            for (int mt = 0; mt < 2; mt++) {
                const uint32_t off = SW128((uint32_t)((arow + mt * 16) * 128) + kb + acolb);
                ldsm4(ah[mt], s0 + OFF_AH + off);
            }
            uint32_t bh[4][4];
#pragma unroll
            for (int p = 0; p < 4; p++) {
                const uint32_t off = SW128((uint32_t)((brow + p * 16) * 128) + kb + bcolb);
                ldsm4(bh[p], s0 + OFF_BH + off);
            }
#pragma unroll
            for (int mt = 0; mt < 2; mt++)
#pragma unroll
                for (int p = 0; p < 4; p++)
#pragma unroll
                    for (int hf = 0; hf < 2; hf++)
                        mma_f16(acc[mt][p * 2 + hf], ah[mt], bh[p][hf * 2], bh[p][hf * 2 + 1]);
        }

        if (it + 2 < NITER) cp_wait<1>(); else cp_wait<0>();
        __syncthreads();
    }

    // epilogue: fp32 (+resid) or hi-only fp16 routed by n0>>10
    const int sel = n0 >> 10;
    const int nl = n0 & (D_DIM - 1);
    __half* Oh = (sel == 0) ? O0h : (sel == 1) ? O1h : O2h;
#pragma unroll
    for (int mt = 0; mt < 2; mt++) {
        const int row0 = m0 + warp_m * 32 + mt * 16 + (lane >> 2);
#pragma unroll
        for (int nt = 0; nt < 8; nt++) {
            const int coll = nl + warp_n * 64 + nt * 8 + (lane & 3) * 2;
            const float* c = acc[mt][nt];
            const size_t off = (size_t)row0 * D_DIM + coll;
            if (Cf) {
                float2 v0 = make_float2(c[0], c[1]);
                float2 v1 = make_float2(c[2], c[3]);
                if (resid) {
                    const float2 r0 = *(const float2*)&resid[off];
                    const float2 r1 = *(const float2*)&resid[off + 8 * D_DIM];
                    v0.x += r0.x; v0.y += r0.y; v1.x += r1.x; v1.y += r1.y;
                }
                *(float2*)&Cf[off] = v0;
                *(float2*)&Cf[off + 8 * D_DIM] = v1;
            } else {
                *(uint32_t*)&Oh[off] = pack_f16(c[0], c[1]);
                *(uint32_t*)&Oh[off + 8 * D_DIM] = pack_f16(c[2], c[3]);
            }
        }
    }
}

// ---------------------------------------------------------------------------
// Tensor-core flash attention, plain fp16 internals. R17: hybrid exp —
// half the values on MUFU ex2, half on an FMA-pipe poly, splitting the
// softmax load across the two idle-capacity pipes (ncu: mufu-bound block,
// fma only 20%). 64 q-rows / 128 threads / 4 warps, 3 CTAs/SM.
// ---------------------------------------------------------------------------
#define ATT_SMEM (8192 + 3 * 16384)    // 57344
#define SLOG2E 0.1803368801111204f     // 0.125 * log2(e)
#define NKV (S_LEN / 64)               // 32

__device__ __forceinline__ void attn_kv_load(
    uint32_t sbase, int tid, size_t kvbase, int k0,
    const __half* kh, const __half* vh)
{
#pragma unroll
    for (int c = tid; c < 512; c += 128) {
        const int row = c >> 3, ch = c & 7;
        const uint32_t sw = SW128((uint32_t)(row * 128 + ch * 16));
        const size_t g = kvbase + (size_t)(k0 + row) * D_DIM + ch * 8;
        cpa16(sbase + sw, kh + g);
        cpa16(sbase + 8192 + sw, vh + g);
    }
    CP_COMMIT();
}

__global__ __launch_bounds__(128, 3)
void attn_mma(const __half* __restrict__ qh,
              const __half* __restrict__ kh, const __half* __restrict__ vh,
              __half* __restrict__ zh)
{
    extern __shared__ __align__(128) char smem[];
    const uint32_t sb = smem_u32(smem);
    const int tid = threadIdx.x, wid = tid >> 5, lane = tid & 31;
    const int q0 = blockIdx.x * 64;
    const int h = blockIdx.y, b = blockIdx.z;
    const size_t qbase = ((size_t)(b * S_LEN + q0)) * D_DIM + h * DH;
    const size_t kvbase = ((size_t)b * S_LEN) * D_DIM + h * DH;
    const int phase = (blockIdx.x & 3) * (NKV / 4);

    // Q load (64 rows x 8 chunks = 512)
#pragma unroll
    for (int c = tid; c < 512; c += 128) {
        const int row = c >> 3, ch = c & 7;
        const uint32_t sw = SW128((uint32_t)(row * 128 + ch * 16));
        cpa16(sb + sw, qh + qbase + (size_t)row * D_DIM + ch * 8);
    }
    CP_COMMIT();
    attn_kv_load(sb + 8192, tid, kvbase, (phase & (NKV - 1)) * 64, kh, vh);
    attn_kv_load(sb + 8192 + 16384, tid, kvbase, ((phase + 1) & (NKV - 1)) * 64, kh, vh);
    cp_wait<1>();
    __syncthreads();

    const int arow = wid * 16 + (lane & 15);
    const uint32_t acolb = (uint32_t)((lane >> 4) << 4);
    const int bnrow = ((lane >> 4) << 3) + (lane & 7);
    const uint32_t bncol = (uint32_t)(((lane >> 3) & 1) << 4);
    const int vrow = ((lane >> 3) & 1) * 8 + (lane & 7);
    const uint32_t vcolb = (uint32_t)((lane >> 4) << 4);

    uint32_t qf[4][4];
#pragma unroll
    for (int ks = 0; ks < 4; ks++) {
        const uint32_t off = SW128((uint32_t)(arow * 128) + (uint32_t)(ks * 32) + acolb);
        ldsm4(qf[ks], sb + off);
    }

    float O[8][4];
#pragma unroll
    for (int nt = 0; nt < 8; nt++)
#pragma unroll
        for (int i = 0; i < 4; i++) O[nt][i] = 0.f;
    float m0 = -1.0e30f, m1 = -1.0e30f, l0 = 0.f, l1 = 0.f;

    for (int tt = 0; tt < NKV; tt++) {
        if (tt + 2 < NKV)
            attn_kv_load(sb + 8192 + ((tt + 2) % 3) * 16384, tid, kvbase,
                         ((tt + 2 + phase) & (NKV - 1)) * 64, kh, vh);

        const uint32_t kbB = sb + 8192 + (tt % 3) * 16384;

        // ---- S = Q K^T, fp32 accum
        float S[8][4];
#pragma unroll
        for (int nt = 0; nt < 8; nt++)
#pragma unroll
            for (int i = 0; i < 4; i++) S[nt][i] = 0.f;
#pragma unroll
        for (int ks = 0; ks < 4; ks++) {
            uint32_t bh_[4][4];
#pragma unroll
            for (int p = 0; p < 4; p++) {
                const uint32_t off = SW128((uint32_t)((p * 16 + bnrow) * 128) + (uint32_t)(ks * 32) + bncol);
                ldsm4(bh_[p], kbB + off);
            }
#pragma unroll
            for (int p = 0; p < 4; p++)
#pragma unroll
                for (int hf = 0; hf < 2; hf++)
                    mma_f16(S[p * 2 + hf], qf[ks], bh_[p][hf * 2], bh_[p][hf * 2 + 1]);
        }

        // ---- online softmax (hybrid: MUFU for nt<4, FMA-pipe poly for nt>=4)
        float mx0 = -1.0e30f, mx1 = -1.0e30f;
#pragma unroll
        for (int nt = 0; nt < 8; nt++) {
            mx0 = fmaxf(mx0, fmaxf(S[nt][0], S[nt][1]));
            mx1 = fmaxf(mx1, fmaxf(S[nt][2], S[nt][3]));
        }
        mx0 = fmaxf(mx0, __shfl_xor_sync(0xffffffffu, mx0, 1));
        mx0 = fmaxf(mx0, __shfl_xor_sync(0xffffffffu, mx0, 2));
        mx1 = fmaxf(mx1, __shfl_xor_sync(0xffffffffu, mx1, 1));
        mx1 = fmaxf(mx1, __shfl_xor_sync(0xffffffffu, mx1, 2));
        const float mn0 = fmaxf(m0, mx0), mn1 = fmaxf(m1, mx1);
        const float mb0 = mn0 * SLOG2E, mb1 = mn1 * SLOG2E;
        const float a0 = ex2_mufu(fmaf(m0, SLOG2E, -mb0));   // exact 1.0 when max unchanged
        const float a1 = ex2_mufu(fmaf(m1, SLOG2E, -mb1));
        m0 = mn0; m1 = mn1;

        float s0 = 0.f, s1 = 0.f;
#pragma unroll
        for (int nt = 0; nt < 8; nt++) {
            if (nt < 4) {
                S[nt][0] = ex2_mufu(fmaf(S[nt][0], SLOG2E, -mb0));
                S[nt][1] = ex2_mufu(fmaf(S[nt][1], SLOG2E, -mb0));
                S[nt][2] = ex2_mufu(fmaf(S[nt][2], SLOG2E, -mb1));
                S[nt][3] = ex2_mufu(fmaf(S[nt][3], SLOG2E, -mb1));
            } else {
                S[nt][0] = ex2_poly(fmaf(S[nt][0], SLOG2E, -mb0));
                S[nt][1] = ex2_poly(fmaf(S[nt][1], SLOG2E, -mb0));
                S[nt][2] = ex2_poly(fmaf(S[nt][2], SLOG2E, -mb1));
                S[nt][3] = ex2_poly(fmaf(S[nt][3], SLOG2E, -mb1));
            }
            s0 += S[nt][0] + S[nt][1];
            s1 += S[nt][2] + S[nt][3];
        }
        l0 = l0 * a0 + s0;
        l1 = l1 * a1 + s1;

        if (__ballot_sync(0xffffffffu, (a0 != 1.0f) || (a1 != 1.0f))) {
#pragma unroll
            for (int nt = 0; nt < 8; nt++) {
                O[nt][0] *= a0; O[nt][1] *= a0; O[nt][2] *= a1; O[nt][3] *= a1;
            }
        }

        // ---- P fragments (hi-only) in registers
        uint32_t pf[4][4];
#pragma unroll
        for (int ks = 0; ks < 4; ks++) {
            pf[ks][0] = pack_f16(S[2 * ks][0], S[2 * ks][1]);
            pf[ks][1] = pack_f16(S[2 * ks][2], S[2 * ks][3]);
            pf[ks][2] = pack_f16(S[2 * ks + 1][0], S[2 * ks + 1][1]);
            pf[ks][3] = pack_f16(S[2 * ks + 1][2], S[2 * ks + 1][3]);
        }

        // ---- O += P Vh
#pragma unroll
        for (int ks = 0; ks < 4; ks++) {
            uint32_t vh_[4][4];
#pragma unroll
            for (int p = 0; p < 4; p++) {
                const uint32_t off = SW128((uint32_t)((ks * 16 + vrow) * 128) + (uint32_t)(p * 32) + vcolb);
                ldsm4t(vh_[p], kbB + 8192 + off);
            }
#pragma unroll
            for (int p = 0; p < 4; p++)
#pragma unroll
                for (int hf = 0; hf < 2; hf++)
                    mma_f16(O[p * 2 + hf], pf[ks], vh_[p][hf * 2], vh_[p][hf * 2 + 1]);
        }

        if (tt + 2 < NKV) cp_wait<1>(); else cp_wait<0>();
        __syncthreads();
    }

    l0 += __shfl_xor_sync(0xffffffffu, l0, 1);
    l0 += __shfl_xor_sync(0xffffffffu, l0, 2);
    l1 += __shfl_xor_sync(0xffffffffu, l1, 1);
    l1 += __shfl_xor_sync(0xffffffffu, l1, 2);
    const float inv0 = 1.0f / l0, inv1 = 1.0f / l1;

    const int rowg = b * S_LEN + q0 + wid * 16 + (lane >> 2);
#pragma unroll
    for (int nt = 0; nt < 8; nt++) {
        const int col = h * DH + nt * 8 + (lane & 3) * 2;
        size_t off = (size_t)rowg * D_DIM + col;
        *(uint32_t*)&zh[off] = pack_f16(O[nt][0] * inv0, O[nt][1] * inv0);
        *(uint32_t*)&zh[off + 8 * D_DIM] = pack_f16(O[nt][2] * inv1, O[nt][3] * inv1);
    }
}

// ---------------------------------------------------------------------------
// Inputs (metadata order): x, mask(bool, unused), Wq, Wk, Wv, Wout
// ---------------------------------------------------------------------------
extern "C" void kernel_launch(void* const* d_in, const int* in_sizes, int n_in,
                              void* d_out, int out_size)
{
    (void)in_sizes; (void)n_in; (void)out_size;
    const float* x    = (const float*)d_in[0];
    const float* Wq   = (const float*)d_in[2];
    const float* Wk   = (const float*)d_in[3];
    const float* Wv   = (const float*)d_in[4];
    const float* Wout = (const float*)d_in[5];
    float* out = (float*)d_out;

    __half *xh, *qh, *kh, *vh, *zh, *wth;
    cudaGetSymbolAddress((void**)&xh, g_xh);
    cudaGetSymbolAddress((void**)&qh, g_qh);
    cudaGetSymbolAddress((void**)&kh, g_kh);
    cudaGetSymbolAddress((void**)&vh, g_vh);
    cudaGetSymbolAddress((void**)&zh, g_zh);
    cudaGetSymbolAddress((void**)&wth, g_wth);

    const int NW = D_DIM * D_DIM;

    // 1) cast x to fp16; transpose weights
    k_cast<<<(MROWS * D_DIM + 255) / 256, 256>>>(x, xh, MROWS * D_DIM);
    k_tsplit4<<<dim3(D_DIM / 32, D_DIM / 32, 4), dim3(32, 8)>>>(Wq, Wk, Wv, Wout, wth);

    // 2) merged QKV projection (N=3072), plain fp16, 2 CTAs/SM
    cudaFuncSetAttribute(gemm_f16, cudaFuncAttributeMaxDynamicSharedMemorySize, GEMM_SMEM);
    gemm_f16<<<dim3(3 * D_DIM / TILE_N, MROWS / TILE_M), 256, GEMM_SMEM>>>(
        xh, wth, nullptr, nullptr, qh, kh, vh);

    // 3) tensor-core flash attention (hybrid exp) -> zh
    cudaFuncSetAttribute(attn_mma, cudaFuncAttributeMaxDynamicSharedMemorySize, ATT_SMEM);
    attn_mma<<<dim3(S_LEN / 64, H_NUM, B_NUM), 128, ATT_SMEM>>>(qh, kh, vh, zh);

    // 4) output projection + residual -> fp32 out
    gemm_f16<<<dim3(D_DIM / TILE_N, MROWS / TILE_M), 256, GEMM_SMEM>>>(
        zh, wth + 3 * (size_t)NW, x, out, nullptr, nullptr, nullptr);
}